// round 1
// baseline (speedup 1.0000x reference)
#include <cuda_runtime.h>
#include <math.h>

// Problem dims
#define Bz   32
#define Tz   32
#define Nz   256
#define FIN  32
#define FOUT 32
#define Hz   256
#define INz  8192   // Nz * FOUT
#define G4   1024   // 4 * Hz
#define GM   1024   // Bz * Tz
#define GK   8192
#define GN   1024

// Scratch (static device globals; no allocation)
__device__ float g_gat[(size_t)GM * INz];    // 33.5 MB: GAT output / LSTM input seq
__device__ float g_gates[(size_t)GM * G4];   // 4 MB: seq @ W_ih^T + (b_ih+b_hh)
__device__ float g_hlast[Bz * Hz];           // final hidden state

// ---------------------------------------------------------------------------
// Kernel 1: GAT per (b,t). One block per (b,t), thread = target node i.
// h = x@W in smem; online (no-max) masked softmax over sources j.
// ---------------------------------------------------------------------------
__global__ __launch_bounds__(256) void gat_kernel(
    const float* __restrict__ x, const float* __restrict__ adj,
    const float* __restrict__ W, const float* __restrict__ a_src,
    const float* __restrict__ a_dst, const float* __restrict__ gat_b)
{
    __shared__ float sh[Nz][36];   // padded to 36 floats: 16B-aligned rows, conflict-free writes
    __shared__ float ssrc[Nz];
    __shared__ float sW[FIN][FOUT];
    __shared__ float sas[FOUT], sad[FOUT], sbias[FOUT];

    const int bt  = blockIdx.x;
    const int tid = threadIdx.x;
    const float* xb   = x   + (size_t)bt * Nz * FIN;
    const float* adjb = adj + (size_t)bt * Nz * Nz;

    for (int i = tid; i < FIN * FOUT; i += 256) sW[i / FOUT][i % FOUT] = W[i];
    if (tid < FOUT) { sas[tid] = a_src[tid]; sad[tid] = a_dst[tid]; sbias[tid] = gat_b[tid]; }
    __syncthreads();

    // h row for node tid
    float xv[FIN];
#pragma unroll
    for (int k = 0; k < FIN; k++) xv[k] = xb[tid * FIN + k];
    float vsrc = 0.f, vdst = 0.f;
#pragma unroll
    for (int o = 0; o < FOUT; o++) {
        float acc = 0.f;
#pragma unroll
        for (int k = 0; k < FIN; k++) acc = fmaf(xv[k], sW[k][o], acc);
        sh[tid][o] = acc;
        vsrc = fmaf(acc, sas[o], vsrc);
        vdst = fmaf(acc, sad[o], vdst);
    }
    ssrc[tid] = vsrc;
    __syncthreads();

    // softmax-weighted aggregation for target i = tid over sources j
    float l = 0.f;
    float acc[FOUT];
#pragma unroll
    for (int o = 0; o < FOUT; o++) acc[o] = 0.f;

#pragma unroll 4
    for (int j = 0; j < Nz; j++) {
        float av = adjb[j * Nz + tid];          // adj[j][i]  (mask = adj^T != 0)
        if (av != 0.f || j == tid) {            // + self loop
            float e = vdst + ssrc[j];
            e = (e > 0.f) ? e : 0.2f * e;       // leaky relu, slope 0.2
            float p = __expf(e);                // |e| small -> no max-subtraction needed
            l += p;
            const float4* hj = (const float4*)&sh[j][0];   // broadcast reads
#pragma unroll
            for (int q = 0; q < 8; q++) {
                float4 hv = hj[q];
                acc[4*q+0] = fmaf(p, hv.x, acc[4*q+0]);
                acc[4*q+1] = fmaf(p, hv.y, acc[4*q+1]);
                acc[4*q+2] = fmaf(p, hv.z, acc[4*q+2]);
                acc[4*q+3] = fmaf(p, hv.w, acc[4*q+3]);
            }
        }
    }
    float inv = 1.f / l;   // l > 0 always (self loop)
    float* outp = g_gat + (size_t)bt * INz + tid * FOUT;
#pragma unroll
    for (int o = 0; o < FOUT; o++) outp[o] = fmaf(acc[o], inv, sbias[o]);
}

// ---------------------------------------------------------------------------
// Kernel 2: gates_pre[m][g] = sum_k seq[m][k] * W_ih[g][k] + (b_ih[g]+b_hh[g])
// NT SGEMM: M=N=1024, K=8192. 64x64 block tile, 4x4 microtile, BK=16,
// register double-buffered global loads, kk-major smem (broadcast A reads).
// ---------------------------------------------------------------------------
__global__ __launch_bounds__(256) void gemm_kernel(
    const float* __restrict__ Bmat,   // W_ih [GN][GK]
    const float* __restrict__ b_ih, const float* __restrict__ b_hh)
{
    __shared__ float As[16][68];
    __shared__ float Bs[16][68];

    const int tx = threadIdx.x & 15;   // n dir
    const int ty = threadIdx.x >> 4;   // m dir
    const int m0 = blockIdx.y * 64;
    const int n0 = blockIdx.x * 64;
    const int lr = threadIdx.x >> 2;   // 0..63 (tile row)
    const int lc = threadIdx.x & 3;    // 0..3  (float4 column)

    const float* Aptr = g_gat + (size_t)(m0 + lr) * GK + lc * 4;
    const float* Bptr = Bmat  + (size_t)(n0 + lr) * GK + lc * 4;

    float4 aReg = *(const float4*)Aptr;
    float4 bReg = *(const float4*)Bptr;

    float acc[4][4];
#pragma unroll
    for (int i = 0; i < 4; i++)
#pragma unroll
        for (int j = 0; j < 4; j++) acc[i][j] = 0.f;

    for (int k0 = 0; k0 < GK; k0 += 16) {
        As[lc*4+0][lr] = aReg.x; As[lc*4+1][lr] = aReg.y;
        As[lc*4+2][lr] = aReg.z; As[lc*4+3][lr] = aReg.w;
        Bs[lc*4+0][lr] = bReg.x; Bs[lc*4+1][lr] = bReg.y;
        Bs[lc*4+2][lr] = bReg.z; Bs[lc*4+3][lr] = bReg.w;
        __syncthreads();

        if (k0 + 16 < GK) {   // prefetch next tile into registers
            aReg = *(const float4*)(Aptr + k0 + 16);
            bReg = *(const float4*)(Bptr + k0 + 16);
        }

#pragma unroll
        for (int kk = 0; kk < 16; kk++) {
            float4 av = *(const float4*)&As[kk][ty * 4];
            float4 bv = *(const float4*)&Bs[kk][tx * 4];
            float am[4] = {av.x, av.y, av.z, av.w};
            float bn[4] = {bv.x, bv.y, bv.z, bv.w};
#pragma unroll
            for (int i = 0; i < 4; i++)
#pragma unroll
                for (int j = 0; j < 4; j++)
                    acc[i][j] = fmaf(am[i], bn[j], acc[i][j]);
        }
        __syncthreads();
    }

#pragma unroll
    for (int i = 0; i < 4; i++) {
        int m = m0 + ty * 4 + i;
#pragma unroll
        for (int j = 0; j < 4; j++) {
            int n = n0 + tx * 4 + j;
            g_gates[(size_t)m * GN + n] = acc[i][j] + b_ih[n] + b_hh[n];
        }
    }
}

// ---------------------------------------------------------------------------
// Kernel 3: LSTM recurrence. One block per batch (independent), 1024 threads,
// thread = one gate row; h in smem, c in registers of threads < Hz.
// ---------------------------------------------------------------------------
__global__ __launch_bounds__(1024) void lstm_kernel(const float* __restrict__ W_hh)
{
    __shared__ float hbuf[Hz];
    __shared__ float gbuf[G4];

    const int b   = blockIdx.x;
    const int tid = threadIdx.x;
    if (tid < Hz) hbuf[tid] = 0.f;
    float c = 0.f;

    const float4* wrow = (const float4*)(W_hh + (size_t)tid * Hz);
    const float*  pre  = g_gates + (size_t)b * Tz * G4;
    __syncthreads();

    for (int t = 0; t < Tz; t++) {
        float acc = pre[t * G4 + tid];
        const float4* hv = (const float4*)hbuf;
#pragma unroll 8
        for (int k = 0; k < Hz / 4; k++) {
            float4 w  = wrow[k];
            float4 h4 = hv[k];
            acc = fmaf(w.x, h4.x, acc);
            acc = fmaf(w.y, h4.y, acc);
            acc = fmaf(w.z, h4.z, acc);
            acc = fmaf(w.w, h4.w, acc);
        }
        gbuf[tid] = acc;
        __syncthreads();
        if (tid < Hz) {
            float gi = 1.f / (1.f + __expf(-gbuf[tid]));
            float gf = 1.f / (1.f + __expf(-gbuf[Hz + tid]));
            float gg = tanhf(gbuf[2 * Hz + tid]);
            float go = 1.f / (1.f + __expf(-gbuf[3 * Hz + tid]));
            c = gf * c + gi * gg;
            hbuf[tid] = go * tanhf(c);
        }
        __syncthreads();
    }
    if (tid < Hz) g_hlast[b * Hz + tid] = hbuf[tid];
}

// ---------------------------------------------------------------------------
// Kernel 4: out[b][n] = dot(h_last[b], Wo[n]) + bo[n]
// ---------------------------------------------------------------------------
__global__ __launch_bounds__(256) void out_kernel(
    const float* __restrict__ Wo, const float* __restrict__ bo,
    float* __restrict__ out)
{
    const int b = blockIdx.x, n = threadIdx.x;
    const float4* h4 = (const float4*)(g_hlast + b * Hz);
    const float4* w4 = (const float4*)(Wo + n * Hz);
    float acc = bo[n];
#pragma unroll 8
    for (int k = 0; k < Hz / 4; k++) {
        float4 w = w4[k], h = h4[k];
        acc = fmaf(w.x, h.x, acc);
        acc = fmaf(w.y, h.y, acc);
        acc = fmaf(w.z, h.z, acc);
        acc = fmaf(w.w, h.w, acc);
    }
    out[b * Nz + n] = acc;
}

// ---------------------------------------------------------------------------
extern "C" void kernel_launch(void* const* d_in, const int* in_sizes, int n_in,
                              void* d_out, int out_size)
{
    const float* x     = (const float*)d_in[0];
    const float* adj   = (const float*)d_in[1];
    const float* W     = (const float*)d_in[2];
    const float* a_src = (const float*)d_in[3];
    const float* a_dst = (const float*)d_in[4];
    const float* gat_b = (const float*)d_in[5];
    const float* W_ih  = (const float*)d_in[6];
    const float* W_hh  = (const float*)d_in[7];
    const float* b_ih  = (const float*)d_in[8];
    const float* b_hh  = (const float*)d_in[9];
    const float* Wo    = (const float*)d_in[10];
    const float* bo    = (const float*)d_in[11];
    float* out = (float*)d_out;

    gat_kernel<<<GM, 256>>>(x, adj, W, a_src, a_dst, gat_b);

    dim3 gg(GN / 64, GM / 64);
    gemm_kernel<<<gg, 256>>>(W_ih, b_ih, b_hh);

    lstm_kernel<<<Bz, 1024>>>(W_hh);

    out_kernel<<<Bz, 256>>>(Wo, bo, out);
}

// round 3
// speedup vs baseline: 1.1286x; 1.1286x over previous
#include <cuda_runtime.h>
#include <cuda_bf16.h>
#include <math.h>
#include <stdint.h>

// Problem dims
#define Bz   32
#define Tz   32
#define Nz   256
#define FIN  32
#define FOUT 32
#define Hz   256
#define INz  8192
#define G4   1024
#define GM   1024   // Bz*Tz rows of seq
#define GK   8192
#define GN   1024

// GEMM tiling
#define BM 128
#define BN 64
#define BK 64
#define NIT (GK / BK)          // 128
#define STAGE_B 49152          // Ah(16K)+Al(16K)+Bh(8K)+Bl(8K)
#define OFF_AL 16384
#define OFF_BH 32768
#define OFF_BL 40960
#define SMEM_DYN (3 * STAGE_B) // 144 KB

// ---------------------------------------------------------------------------
// Scratch (static device globals)
// ---------------------------------------------------------------------------
__device__ __nv_bfloat16 g_seq_hi[(size_t)GM * GK];
__device__ __nv_bfloat16 g_seq_lo[(size_t)GM * GK];
__device__ __nv_bfloat16 g_wih_hi[(size_t)GN * GK];
__device__ __nv_bfloat16 g_wih_lo[(size_t)GN * GK];
__device__ float g_gates[(size_t)GM * G4];
__device__ float g_hlast[Bz * Hz];

// ---------------------------------------------------------------------------
// PTX helpers (baseline sm_80 features only — no 'a'-suffix instructions)
// ---------------------------------------------------------------------------
__device__ __forceinline__ uint32_t smem_u32(const void* p) {
    return (uint32_t)__cvta_generic_to_shared(p);
}

#define CP_ASYNC16(dst, src) \
    asm volatile("cp.async.cg.shared.global [%0], [%1], 16;" :: "r"(dst), "l"(src) : "memory")
#define CP_COMMIT() asm volatile("cp.async.commit_group;" ::: "memory")
#define CP_WAIT1()  asm volatile("cp.async.wait_group 1;" ::: "memory")
#define CP_WAIT0()  asm volatile("cp.async.wait_group 0;" ::: "memory")

#define LDSM_X4(r0, r1, r2, r3, addr) \
    asm volatile("ldmatrix.sync.aligned.m8n8.x4.shared.b16 {%0,%1,%2,%3}, [%4];" \
        : "=r"(r0), "=r"(r1), "=r"(r2), "=r"(r3) : "r"(addr))

__device__ __forceinline__ void mma16816(float* d, const uint32_t* a, const uint32_t* b) {
    asm volatile(
        "mma.sync.aligned.m16n8k16.row.col.f32.bf16.bf16.f32 "
        "{%0,%1,%2,%3}, {%4,%5,%6,%7}, {%8,%9}, {%0,%1,%2,%3};"
        : "+f"(d[0]), "+f"(d[1]), "+f"(d[2]), "+f"(d[3])
        : "r"(a[0]), "r"(a[1]), "r"(a[2]), "r"(a[3]), "r"(b[0]), "r"(b[1]));
}

__device__ __forceinline__ uint32_t pack_bf16x2(float v0, float v1) {
    unsigned short a = __bfloat16_as_ushort(__float2bfloat16(v0));
    unsigned short b = __bfloat16_as_ushort(__float2bfloat16(v1));
    return ((uint32_t)b << 16) | a;
}
__device__ __forceinline__ void split_bf16(float v, float& hi, float& lo) {
    __nv_bfloat16 h = __float2bfloat16(v);
    hi = __bfloat162float(h);
    lo = v - hi;
}

// ---------------------------------------------------------------------------
// Kernel 1: GAT per (b,t). Writes seq as row-major bf16 hi/lo.
// ---------------------------------------------------------------------------
__global__ __launch_bounds__(256) void gat_kernel(
    const float* __restrict__ x, const float* __restrict__ adj,
    const float* __restrict__ W, const float* __restrict__ a_src,
    const float* __restrict__ a_dst, const float* __restrict__ gat_b)
{
    __shared__ float sh[Nz][36];
    __shared__ float ssrc[Nz];
    __shared__ float sW[FIN][FOUT];
    __shared__ float sas[FOUT], sad[FOUT], sbias[FOUT];

    const int bt  = blockIdx.x;
    const int tid = threadIdx.x;
    const float* xb   = x   + (size_t)bt * Nz * FIN;
    const float* adjb = adj + (size_t)bt * Nz * Nz;

    for (int i = tid; i < FIN * FOUT; i += 256) sW[i / FOUT][i % FOUT] = W[i];
    if (tid < FOUT) { sas[tid] = a_src[tid]; sad[tid] = a_dst[tid]; sbias[tid] = gat_b[tid]; }
    __syncthreads();

    float xv[FIN];
#pragma unroll
    for (int k = 0; k < FIN; k++) xv[k] = xb[tid * FIN + k];
    float vsrc = 0.f, vdst = 0.f;
#pragma unroll
    for (int o = 0; o < FOUT; o++) {
        float acc = 0.f;
#pragma unroll
        for (int k = 0; k < FIN; k++) acc = fmaf(xv[k], sW[k][o], acc);
        sh[tid][o] = acc;
        vsrc = fmaf(acc, sas[o], vsrc);
        vdst = fmaf(acc, sad[o], vdst);
    }
    ssrc[tid] = vsrc;
    __syncthreads();

    float l = 0.f;
    float acc[FOUT];
#pragma unroll
    for (int o = 0; o < FOUT; o++) acc[o] = 0.f;

#pragma unroll 4
    for (int j = 0; j < Nz; j++) {
        float av = adjb[j * Nz + tid];
        if (av != 0.f || j == tid) {
            float e = vdst + ssrc[j];
            e = (e > 0.f) ? e : 0.2f * e;
            float p = __expf(e);
            l += p;
            const float4* hj = (const float4*)&sh[j][0];
#pragma unroll
            for (int q = 0; q < 8; q++) {
                float4 hv = hj[q];
                acc[4*q+0] = fmaf(p, hv.x, acc[4*q+0]);
                acc[4*q+1] = fmaf(p, hv.y, acc[4*q+1]);
                acc[4*q+2] = fmaf(p, hv.z, acc[4*q+2]);
                acc[4*q+3] = fmaf(p, hv.w, acc[4*q+3]);
            }
        }
    }
    float inv = 1.f / l;
    float vh[FOUT], vl[FOUT];
#pragma unroll
    for (int o = 0; o < FOUT; o++) {
        float v = fmaf(acc[o], inv, sbias[o]);
        split_bf16(v, vh[o], vl[o]);
    }

    // row m = bt, k = tid*32 + o, row-major
    size_t off = (size_t)bt * GK + (size_t)tid * FOUT;
    uint4* ph = (uint4*)(g_seq_hi + off);
    uint4* pl = (uint4*)(g_seq_lo + off);
#pragma unroll
    for (int g = 0; g < 4; g++) {
        uint4 uh, ul;
        uh.x = pack_bf16x2(vh[g*8+0], vh[g*8+1]);
        uh.y = pack_bf16x2(vh[g*8+2], vh[g*8+3]);
        uh.z = pack_bf16x2(vh[g*8+4], vh[g*8+5]);
        uh.w = pack_bf16x2(vh[g*8+6], vh[g*8+7]);
        ul.x = pack_bf16x2(vl[g*8+0], vl[g*8+1]);
        ul.y = pack_bf16x2(vl[g*8+2], vl[g*8+3]);
        ul.z = pack_bf16x2(vl[g*8+4], vl[g*8+5]);
        ul.w = pack_bf16x2(vl[g*8+6], vl[g*8+7]);
        ph[g] = uh;
        pl[g] = ul;
    }
}

// ---------------------------------------------------------------------------
// Kernel 1b: W_ih fp32 -> bf16 hi/lo (row-major)
// ---------------------------------------------------------------------------
__global__ __launch_bounds__(256) void conv_wih_kernel(const float* __restrict__ W_ih)
{
    size_t t = (size_t)blockIdx.x * 256 + threadIdx.x;   // one per 8 elems
    size_t e0 = t * 8;
    const float* src = W_ih + e0;
    float4 v0 = *(const float4*)(src);
    float4 v1 = *(const float4*)(src + 4);
    float f[8] = {v0.x, v0.y, v0.z, v0.w, v1.x, v1.y, v1.z, v1.w};
    float fh[8], fl[8];
#pragma unroll
    for (int i = 0; i < 8; i++) split_bf16(f[i], fh[i], fl[i]);
    uint4 uh, ul;
    uh.x = pack_bf16x2(fh[0], fh[1]); uh.y = pack_bf16x2(fh[2], fh[3]);
    uh.z = pack_bf16x2(fh[4], fh[5]); uh.w = pack_bf16x2(fh[6], fh[7]);
    ul.x = pack_bf16x2(fl[0], fl[1]); ul.y = pack_bf16x2(fl[2], fl[3]);
    ul.z = pack_bf16x2(fl[4], fl[5]); ul.w = pack_bf16x2(fl[6], fl[7]);
    *(uint4*)(g_wih_hi + e0) = uh;
    *(uint4*)(g_wih_lo + e0) = ul;
}

// ---------------------------------------------------------------------------
// Kernel 2: split-bf16 tensor-core GEMM via mma.sync.
// C[m][n] = sum_k seq[m][k] * W_ih[n][k]; CTA tile 128x64, BK=64, 3 stages.
// ---------------------------------------------------------------------------
__global__ __launch_bounds__(256) void tc_gemm_kernel(
    const float* __restrict__ b_ih, const float* __restrict__ b_hh)
{
    extern __shared__ __align__(128) unsigned char dsmem[];
    const uint32_t dsm = smem_u32(dsmem);

    const int tid  = threadIdx.x;
    const int lane = tid & 31;
    const int wid  = tid >> 5;
    const int warp_m = wid >> 1;      // 0..3
    const int warp_n = wid & 1;       // 0..1
    const int mblk = blockIdx.y * BM;
    const int nblk = blockIdx.x * BN;

    // ldmatrix lane geometry
    const int rA  = warp_m * 32 + (lane & 7) + ((lane >> 3) & 1) * 8;  // A row in tile
    const int aHf = lane >> 4;                                         // A k-seg half
    const int r7a = rA & 7;
    const int rB  = warp_n * 32 + (lane & 7) + ((lane >> 4) & 1) * 8;  // B row in tile
    const int bHf = (lane >> 3) & 1;
    const int r7b = rB & 7;
    const uint32_t aoff0 = (uint32_t)rA * 128;
    const uint32_t aoff1 = aoff0 + 16 * 128;
    const uint32_t boff0 = (uint32_t)rB * 128;
    const uint32_t boff1 = boff0 + 16 * 128;

    float d[2][4][4];
#pragma unroll
    for (int i = 0; i < 2; i++)
#pragma unroll
        for (int j = 0; j < 4; j++)
#pragma unroll
            for (int q = 0; q < 4; q++) d[i][j][q] = 0.f;

    // stage loader
    auto load_stage = [&](int st, int it) {
        uint32_t sb = dsm + st * STAGE_B;
        size_t k0 = (size_t)it * BK;
#pragma unroll
        for (int i = 0; i < 4; i++) {          // A: 128 rows x 8 segs
            int c = tid + i * 256;
            int row = c >> 3, seg = c & 7;
            uint32_t dst = sb + row * 128 + (uint32_t)((seg ^ (row & 7)) << 4);
            const __nv_bfloat16* s = g_seq_hi + (size_t)(mblk + row) * GK + k0 + seg * 8;
            CP_ASYNC16(dst, s);
            const __nv_bfloat16* s2 = g_seq_lo + (size_t)(mblk + row) * GK + k0 + seg * 8;
            CP_ASYNC16(dst + OFF_AL, s2);
        }
#pragma unroll
        for (int i = 0; i < 2; i++) {          // B: 64 rows x 8 segs
            int c = tid + i * 256;
            int row = c >> 3, seg = c & 7;
            uint32_t dst = sb + OFF_BH + row * 128 + (uint32_t)((seg ^ (row & 7)) << 4);
            const __nv_bfloat16* s = g_wih_hi + (size_t)(nblk + row) * GK + k0 + seg * 8;
            CP_ASYNC16(dst, s);
            const __nv_bfloat16* s2 = g_wih_lo + (size_t)(nblk + row) * GK + k0 + seg * 8;
            CP_ASYNC16(dst + 8192, s2);
        }
    };

    load_stage(0, 0); CP_COMMIT();
    load_stage(1, 1); CP_COMMIT();

    for (int it = 0; it < NIT; it++) {
        CP_WAIT1();
        __syncthreads();
        int s = it % 3;
        if (it + 2 < NIT) load_stage((it + 2) % 3, it + 2);
        CP_COMMIT();

        uint32_t sA = dsm + s * STAGE_B;
        uint32_t sB = sA + OFF_BH;
#pragma unroll
        for (int ks = 0; ks < 4; ks++) {
            int kseg = ks * 2;
            uint32_t ah[2][4], al[2][4], bh[2][4], bl[2][4];
            {
                uint32_t asg = (uint32_t)(((kseg + aHf) ^ r7a) << 4);
                uint32_t ad0 = sA + aoff0 + asg;
                uint32_t ad1 = sA + aoff1 + asg;
                LDSM_X4(ah[0][0], ah[0][1], ah[0][2], ah[0][3], ad0);
                LDSM_X4(ah[1][0], ah[1][1], ah[1][2], ah[1][3], ad1);
                LDSM_X4(al[0][0], al[0][1], al[0][2], al[0][3], ad0 + OFF_AL);
                LDSM_X4(al[1][0], al[1][1], al[1][2], al[1][3], ad1 + OFF_AL);
            }
            {
                uint32_t bsg = (uint32_t)(((kseg + bHf) ^ r7b) << 4);
                uint32_t bd0 = sB + boff0 + bsg;
                uint32_t bd1 = sB + boff1 + bsg;
                LDSM_X4(bh[0][0], bh[0][1], bh[0][2], bh[0][3], bd0);
                LDSM_X4(bh[1][0], bh[1][1], bh[1][2], bh[1][3], bd1);
                LDSM_X4(bl[0][0], bl[0][1], bl[0][2], bl[0][3], bd0 + 8192);
                LDSM_X4(bl[1][0], bl[1][1], bl[1][2], bl[1][3], bd1 + 8192);
            }
#pragma unroll
            for (int mt = 0; mt < 2; mt++)
#pragma unroll
                for (int p = 0; p < 2; p++)
#pragma unroll
                    for (int hf = 0; hf < 2; hf++) {
                        float* dd = d[mt][p * 2 + hf];
                        mma16816(dd, ah[mt], &bh[p][hf * 2]);
                        mma16816(dd, ah[mt], &bl[p][hf * 2]);
                        mma16816(dd, al[mt], &bh[p][hf * 2]);
                    }
        }
        __syncthreads();
    }

    // epilogue: add biases, store fp32
#pragma unroll
    for (int mt = 0; mt < 2; mt++) {
#pragma unroll
        for (int nt = 0; nt < 4; nt++) {
            int rowm = mblk + warp_m * 32 + mt * 16 + (lane >> 2);
            int coln = nblk + warp_n * 32 + nt * 8 + (lane & 3) * 2;
            float bi0 = b_ih[coln]     + b_hh[coln];
            float bi1 = b_ih[coln + 1] + b_hh[coln + 1];
            float* p0 = g_gates + (size_t)rowm * GN + coln;
            float* p1 = g_gates + (size_t)(rowm + 8) * GN + coln;
            float2 v0 = {d[mt][nt][0] + bi0, d[mt][nt][1] + bi1};
            float2 v1 = {d[mt][nt][2] + bi0, d[mt][nt][3] + bi1};
            *(float2*)p0 = v0;
            *(float2*)p1 = v1;
        }
    }
}

// ---------------------------------------------------------------------------
// Kernel 3: LSTM recurrence
// ---------------------------------------------------------------------------
__global__ __launch_bounds__(1024) void lstm_kernel(const float* __restrict__ W_hh)
{
    __shared__ float hbuf[Hz];
    __shared__ float gbuf[G4];

    const int b   = blockIdx.x;
    const int tid = threadIdx.x;
    if (tid < Hz) hbuf[tid] = 0.f;
    float c = 0.f;

    const float4* wrow = (const float4*)(W_hh + (size_t)tid * Hz);
    const float*  pre  = g_gates + (size_t)b * Tz * G4;
    __syncthreads();

    for (int t = 0; t < Tz; t++) {
        float acc = pre[t * G4 + tid];
        const float4* hv = (const float4*)hbuf;
#pragma unroll 8
        for (int k = 0; k < Hz / 4; k++) {
            float4 w  = wrow[k];
            float4 h4 = hv[k];
            acc = fmaf(w.x, h4.x, acc);
            acc = fmaf(w.y, h4.y, acc);
            acc = fmaf(w.z, h4.z, acc);
            acc = fmaf(w.w, h4.w, acc);
        }
        gbuf[tid] = acc;
        __syncthreads();
        if (tid < Hz) {
            float gi = 1.f / (1.f + __expf(-gbuf[tid]));
            float gf = 1.f / (1.f + __expf(-gbuf[Hz + tid]));
            float gg = tanhf(gbuf[2 * Hz + tid]);
            float go = 1.f / (1.f + __expf(-gbuf[3 * Hz + tid]));
            c = gf * c + gi * gg;
            hbuf[tid] = go * tanhf(c);
        }
        __syncthreads();
    }
    if (tid < Hz) g_hlast[b * Hz + tid] = hbuf[tid];
}

// ---------------------------------------------------------------------------
// Kernel 4: output linear
// ---------------------------------------------------------------------------
__global__ __launch_bounds__(256) void out_kernel(
    const float* __restrict__ Wo, const float* __restrict__ bo,
    float* __restrict__ out)
{
    const int b = blockIdx.x, n = threadIdx.x;
    const float4* h4 = (const float4*)(g_hlast + b * Hz);
    const float4* w4 = (const float4*)(Wo + n * Hz);
    float acc = bo[n];
#pragma unroll 8
    for (int k = 0; k < Hz / 4; k++) {
        float4 w = w4[k], h = h4[k];
        acc = fmaf(w.x, h.x, acc);
        acc = fmaf(w.y, h.y, acc);
        acc = fmaf(w.z, h.z, acc);
        acc = fmaf(w.w, h.w, acc);
    }
    out[b * Nz + n] = acc;
}

// ---------------------------------------------------------------------------
extern "C" void kernel_launch(void* const* d_in, const int* in_sizes, int n_in,
                              void* d_out, int out_size)
{
    const float* x     = (const float*)d_in[0];
    const float* adj   = (const float*)d_in[1];
    const float* W     = (const float*)d_in[2];
    const float* a_src = (const float*)d_in[3];
    const float* a_dst = (const float*)d_in[4];
    const float* gat_b = (const float*)d_in[5];
    const float* W_ih  = (const float*)d_in[6];
    const float* W_hh  = (const float*)d_in[7];
    const float* b_ih  = (const float*)d_in[8];
    const float* b_hh  = (const float*)d_in[9];
    const float* Wo    = (const float*)d_in[10];
    const float* bo    = (const float*)d_in[11];
    float* out = (float*)d_out;

    cudaFuncSetAttribute(tc_gemm_kernel,
                         cudaFuncAttributeMaxDynamicSharedMemorySize, SMEM_DYN);

    conv_wih_kernel<<<(int)(((size_t)GN * GK / 8) / 256), 256>>>(W_ih);
    gat_kernel<<<GM, 256>>>(x, adj, W, a_src, a_dst, gat_b);

    dim3 gg(GN / BN, GM / BM);   // 16 x 8 = 128 CTAs
    tc_gemm_kernel<<<gg, 256, SMEM_DYN>>>(b_ih, b_hh);

    lstm_kernel<<<Bz, 1024>>>(W_hh);

    out_kernel<<<Bz, 256>>>(Wo, bo, out);
}

// round 4
// speedup vs baseline: 1.2945x; 1.1470x over previous
#include <cuda_runtime.h>
#include <cuda_bf16.h>
#include <math.h>
#include <stdint.h>

// Problem dims
#define Bz   32
#define Tz   32
#define Nz   256
#define FIN  32
#define FOUT 32
#define Hz   256
#define INz  8192
#define G4   1024
#define GM   1024   // Bz*Tz rows of seq
#define GK   8192
#define GN   1024

// GEMM tiling
#define BM 128
#define BN 64
#define BK 64
#define NIT (GK / BK)          // 128
#define NSTAGE 3
#define OFF_AL 16384
#define OFF_BH 32768
#define OFF_BL 40960
#define STAGE_B 49152          // Ah16K + Al16K + Bh8K + Bl8K
#define SMEM_DYN (NSTAGE * STAGE_B)   // 144 KB

// ---------------------------------------------------------------------------
// Scratch (static device globals). seq/wih stored in ldmatrix-swizzled tiled
// layout: offset = ((rowtile*128 + kchunk) << 14) + row*128 + ((seg^(row&7))<<4) + (k&7)*2
//   rowtile = r>>7, row = r&127, kchunk = k>>6, seg = (k&63)>>3
// ---------------------------------------------------------------------------
__device__ __align__(128) __nv_bfloat16 g_seq_hi[(size_t)GM * GK];
__device__ __align__(128) __nv_bfloat16 g_seq_lo[(size_t)GM * GK];
__device__ __align__(128) __nv_bfloat16 g_wih_hi[(size_t)GN * GK];
__device__ __align__(128) __nv_bfloat16 g_wih_lo[(size_t)GN * GK];
__device__ float g_gates[(size_t)GM * G4];
__device__ float g_hlast[Bz * Hz];

// ---------------------------------------------------------------------------
// PTX helpers (baseline features only — nothing 'a'-suffix)
// ---------------------------------------------------------------------------
__device__ __forceinline__ uint32_t smem_u32(const void* p) {
    return (uint32_t)__cvta_generic_to_shared(p);
}

#define MBARRIER_INIT(addr, cnt) \
    asm volatile("mbarrier.init.shared.b64 [%0], %1;" :: "r"(addr), "r"(cnt) : "memory")
#define MBARRIER_EXPECT_TX(addr, bytes) \
    asm volatile("mbarrier.arrive.expect_tx.shared.b64 _, [%0], %1;" :: "r"(addr), "r"(bytes) : "memory")
#define MBARRIER_WAIT_PARITY(addr, par) do {                                        \
    uint32_t _mbar = (addr); uint32_t _p = (par); uint32_t _done;                   \
    asm volatile("{\n\t.reg .pred p;\n\t"                                           \
        "mbarrier.try_wait.parity.acquire.cta.shared::cta.b64 p, [%1], %2;\n\t"     \
        "selp.b32 %0, 1, 0, p;\n\t}"                                                \
        : "=r"(_done) : "r"(_mbar), "r"(_p) : "memory");                            \
    if (!_done) {                                                                   \
        asm volatile("{\n\t.reg .pred P1;\n\t"                                      \
            "WAIT_LOOP_%=:\n\t"                                                     \
            "mbarrier.try_wait.parity.acquire.cta.shared::cta.b64 P1, [%0], %1, 0x989680;\n\t" \
            "@P1 bra.uni WAIT_DONE_%=;\n\t"                                         \
            "bra.uni WAIT_LOOP_%=;\n\t"                                             \
            "WAIT_DONE_%=:\n\t}"                                                    \
            :: "r"(_mbar), "r"(_p) : "memory");                                     \
    } } while (0)

#define BULK_G2S(dst, src, bytes, mbar) \
    asm volatile("cp.async.bulk.shared::cluster.global.mbarrier::complete_tx::bytes [%0], [%1], %2, [%3];" \
        :: "r"(dst), "l"(src), "r"(bytes), "r"(mbar) : "memory")

#define FENCE_ASYNC() asm volatile("fence.proxy.async.shared::cta;" ::: "memory")

#define LDSM_X4(r0, r1, r2, r3, addr) \
    asm volatile("ldmatrix.sync.aligned.m8n8.x4.shared.b16 {%0,%1,%2,%3}, [%4];" \
        : "=r"(r0), "=r"(r1), "=r"(r2), "=r"(r3) : "r"(addr))

__device__ __forceinline__ void mma16816(float* d, const uint32_t* a, const uint32_t* b) {
    asm volatile(
        "mma.sync.aligned.m16n8k16.row.col.f32.bf16.bf16.f32 "
        "{%0,%1,%2,%3}, {%4,%5,%6,%7}, {%8,%9}, {%0,%1,%2,%3};"
        : "+f"(d[0]), "+f"(d[1]), "+f"(d[2]), "+f"(d[3])
        : "r"(a[0]), "r"(a[1]), "r"(a[2]), "r"(a[3]), "r"(b[0]), "r"(b[1]));
}

__device__ __forceinline__ uint32_t pack_bf16x2(float v0, float v1) {
    unsigned short a = __bfloat16_as_ushort(__float2bfloat16(v0));
    unsigned short b = __bfloat16_as_ushort(__float2bfloat16(v1));
    return ((uint32_t)b << 16) | a;
}
__device__ __forceinline__ void split_bf16(float v, float& hi, float& lo) {
    __nv_bfloat16 h = __float2bfloat16(v);
    hi = __bfloat162float(h);
    lo = v - hi;
}

// ---------------------------------------------------------------------------
// Kernel 1: GAT per (b,t). Writes seq as swizzled-tiled bf16 hi/lo.
// ---------------------------------------------------------------------------
__global__ __launch_bounds__(256) void gat_kernel(
    const float* __restrict__ x, const float* __restrict__ adj,
    const float* __restrict__ W, const float* __restrict__ a_src,
    const float* __restrict__ a_dst, const float* __restrict__ gat_b)
{
    __shared__ float sh[Nz][36];
    __shared__ float ssrc[Nz];
    __shared__ float sW[FIN][FOUT];
    __shared__ float sas[FOUT], sad[FOUT], sbias[FOUT];

    const int bt  = blockIdx.x;
    const int tid = threadIdx.x;
    const float* xb   = x   + (size_t)bt * Nz * FIN;
    const float* adjb = adj + (size_t)bt * Nz * Nz;

    for (int i = tid; i < FIN * FOUT; i += 256) sW[i / FOUT][i % FOUT] = W[i];
    if (tid < FOUT) { sas[tid] = a_src[tid]; sad[tid] = a_dst[tid]; sbias[tid] = gat_b[tid]; }
    __syncthreads();

    float xv[FIN];
#pragma unroll
    for (int k = 0; k < FIN; k++) xv[k] = xb[tid * FIN + k];
    float vsrc = 0.f, vdst = 0.f;
#pragma unroll
    for (int o = 0; o < FOUT; o++) {
        float acc = 0.f;
#pragma unroll
        for (int k = 0; k < FIN; k++) acc = fmaf(xv[k], sW[k][o], acc);
        sh[tid][o] = acc;
        vsrc = fmaf(acc, sas[o], vsrc);
        vdst = fmaf(acc, sad[o], vdst);
    }
    ssrc[tid] = vsrc;
    __syncthreads();

    float l = 0.f;
    float acc[FOUT];
#pragma unroll
    for (int o = 0; o < FOUT; o++) acc[o] = 0.f;

#pragma unroll 4
    for (int j = 0; j < Nz; j++) {
        float av = adjb[j * Nz + tid];
        if (av != 0.f || j == tid) {
            float e = vdst + ssrc[j];
            e = (e > 0.f) ? e : 0.2f * e;
            float p = __expf(e);
            l += p;
            const float4* hj = (const float4*)&sh[j][0];
#pragma unroll
            for (int q = 0; q < 8; q++) {
                float4 hv = hj[q];
                acc[4*q+0] = fmaf(p, hv.x, acc[4*q+0]);
                acc[4*q+1] = fmaf(p, hv.y, acc[4*q+1]);
                acc[4*q+2] = fmaf(p, hv.z, acc[4*q+2]);
                acc[4*q+3] = fmaf(p, hv.w, acc[4*q+3]);
            }
        }
    }
    float inv = 1.f / l;
    float vh[FOUT], vl[FOUT];
#pragma unroll
    for (int o = 0; o < FOUT; o++) {
        float v = fmaf(acc[o], inv, sbias[o]);
        split_bf16(v, vh[o], vl[o]);
    }

    // write swizzled tiled layout: row m = bt, k = tid*32 + (g*8 + e)
    const int mtile = bt >> 7, mrow = bt & 127;
    const int chunk = tid >> 1;
    const int seg0  = (tid & 1) * 4;
    unsigned char* baseh = (unsigned char*)g_seq_hi + (((size_t)(mtile * 128 + chunk)) << 14) + mrow * 128;
    unsigned char* basel = (unsigned char*)g_seq_lo + (((size_t)(mtile * 128 + chunk)) << 14) + mrow * 128;
#pragma unroll
    for (int g = 0; g < 4; g++) {
        uint32_t sw = (uint32_t)(((seg0 + g) ^ (mrow & 7)) << 4);
        uint4 uh, ul;
        uh.x = pack_bf16x2(vh[g*8+0], vh[g*8+1]);
        uh.y = pack_bf16x2(vh[g*8+2], vh[g*8+3]);
        uh.z = pack_bf16x2(vh[g*8+4], vh[g*8+5]);
        uh.w = pack_bf16x2(vh[g*8+6], vh[g*8+7]);
        ul.x = pack_bf16x2(vl[g*8+0], vl[g*8+1]);
        ul.y = pack_bf16x2(vl[g*8+2], vl[g*8+3]);
        ul.z = pack_bf16x2(vl[g*8+4], vl[g*8+5]);
        ul.w = pack_bf16x2(vl[g*8+6], vl[g*8+7]);
        *(uint4*)(baseh + sw) = uh;
        *(uint4*)(basel + sw) = ul;
    }
}

// ---------------------------------------------------------------------------
// Kernel 1b: W_ih fp32 -> swizzled tiled bf16 hi/lo
// ---------------------------------------------------------------------------
__global__ __launch_bounds__(256) void conv_wih_kernel(const float* __restrict__ W_ih)
{
    size_t t = (size_t)blockIdx.x * 256 + threadIdx.x;   // one per 8 elems (one seg)
    int n = (int)(t >> 10);
    int s = (int)(t & 1023);                             // seg index within row
    int k0 = s * 8;
    const float* src = W_ih + (size_t)n * GK + k0;
    float4 v0 = *(const float4*)(src);
    float4 v1 = *(const float4*)(src + 4);
    float f[8] = {v0.x, v0.y, v0.z, v0.w, v1.x, v1.y, v1.z, v1.w};
    float fh[8], fl[8];
#pragma unroll
    for (int i = 0; i < 8; i++) split_bf16(f[i], fh[i], fl[i]);

    int ntile = n >> 7, nrow = n & 127, chunk = s >> 3, seg = s & 7;
    size_t off = (((size_t)(ntile * 128 + chunk)) << 14) + nrow * 128
               + (uint32_t)((seg ^ (nrow & 7)) << 4);
    uint4 uh, ul;
    uh.x = pack_bf16x2(fh[0], fh[1]); uh.y = pack_bf16x2(fh[2], fh[3]);
    uh.z = pack_bf16x2(fh[4], fh[5]); uh.w = pack_bf16x2(fh[6], fh[7]);
    ul.x = pack_bf16x2(fl[0], fl[1]); ul.y = pack_bf16x2(fl[2], fl[3]);
    ul.z = pack_bf16x2(fl[4], fl[5]); ul.w = pack_bf16x2(fl[6], fl[7]);
    *(uint4*)((unsigned char*)g_wih_hi + off) = uh;
    *(uint4*)((unsigned char*)g_wih_lo + off) = ul;
}

// ---------------------------------------------------------------------------
// Kernel 2: split-bf16 mma.sync GEMM fed by cp.async.bulk + mbarrier.
// C[m][n] = sum_k seq[m][k]*W_ih[n][k]; CTA 128x64, BK=64, 3-stage pipeline.
// ---------------------------------------------------------------------------
__global__ __launch_bounds__(256) void tc_gemm_kernel(
    const float* __restrict__ b_ih, const float* __restrict__ b_hh)
{
    extern __shared__ __align__(128) unsigned char dsmem[];
    __shared__ __align__(8) unsigned long long s_full[NSTAGE];
    const uint32_t dsm = smem_u32(dsmem);

    const int tid  = threadIdx.x;
    const int lane = tid & 31;
    const int wid  = tid >> 5;
    const int warp_m = wid >> 1;      // 0..3
    const int warp_n = wid & 1;       // 0..1
    const int mblk = blockIdx.y * BM;
    const int nblk = blockIdx.x * BN;
    const int mtile = blockIdx.y;               // BM == 128
    const int ntile = blockIdx.x >> 1;
    const size_t bhalf = (size_t)(blockIdx.x & 1) * 8192;

    if (tid == 0) {
        for (int p = 0; p < NSTAGE; p++) MBARRIER_INIT(smem_u32(&s_full[p]), 1);
        FENCE_ASYNC();
    }
    __syncthreads();

    const unsigned char* srcAh = (const unsigned char*)g_seq_hi + (((size_t)mtile * 128) << 14);
    const unsigned char* srcAl = (const unsigned char*)g_seq_lo + (((size_t)mtile * 128) << 14);
    const unsigned char* srcBh = (const unsigned char*)g_wih_hi + (((size_t)ntile * 128) << 14) + bhalf;
    const unsigned char* srcBl = (const unsigned char*)g_wih_lo + (((size_t)ntile * 128) << 14) + bhalf;

    auto issue_stage = [&](int st, int it) {
        uint32_t sb = dsm + st * STAGE_B;
        uint32_t fb = smem_u32(&s_full[st]);
        size_t off = (size_t)it << 14;
        MBARRIER_EXPECT_TX(fb, STAGE_B);
        BULK_G2S(sb,          srcAh + off, 16384, fb);
        BULK_G2S(sb + OFF_AL, srcAl + off, 16384, fb);
        BULK_G2S(sb + OFF_BH, srcBh + off,  8192, fb);
        BULK_G2S(sb + OFF_BL, srcBl + off,  8192, fb);
    };

    if (tid == 0) {
        issue_stage(0, 0);
        issue_stage(1, 1);
        issue_stage(2, 2);
    }

    // ldmatrix lane geometry
    const int rA  = warp_m * 32 + (lane & 7) + ((lane >> 3) & 1) * 8;
    const int aHf = lane >> 4;
    const int r7a = rA & 7;
    const int rB  = warp_n * 32 + (lane & 7) + ((lane >> 4) & 1) * 8;
    const int bHf = (lane >> 3) & 1;
    const int r7b = rB & 7;
    const uint32_t aoff0 = (uint32_t)rA * 128;
    const uint32_t aoff1 = aoff0 + 16 * 128;
    const uint32_t boff0 = (uint32_t)rB * 128;
    const uint32_t boff1 = boff0 + 16 * 128;

    float d[2][4][4];
#pragma unroll
    for (int i = 0; i < 2; i++)
#pragma unroll
        for (int j = 0; j < 4; j++)
#pragma unroll
            for (int q = 0; q < 4; q++) d[i][j][q] = 0.f;

    for (int it = 0; it < NIT; it++) {
        int s = it % NSTAGE;
        MBARRIER_WAIT_PARITY(smem_u32(&s_full[s]), (it / NSTAGE) & 1);

        uint32_t sA = dsm + s * STAGE_B;
        uint32_t sB = sA + OFF_BH;
#pragma unroll
        for (int ks = 0; ks < 4; ks++) {
            int kseg = ks * 2;
            uint32_t ah[2][4], al[2][4], bh[2][4], bl[2][4];
            {
                uint32_t asg = (uint32_t)(((kseg + aHf) ^ r7a) << 4);
                uint32_t ad0 = sA + aoff0 + asg;
                uint32_t ad1 = sA + aoff1 + asg;
                LDSM_X4(ah[0][0], ah[0][1], ah[0][2], ah[0][3], ad0);
                LDSM_X4(ah[1][0], ah[1][1], ah[1][2], ah[1][3], ad1);
                LDSM_X4(al[0][0], al[0][1], al[0][2], al[0][3], ad0 + OFF_AL);
                LDSM_X4(al[1][0], al[1][1], al[1][2], al[1][3], ad1 + OFF_AL);
            }
            {
                uint32_t bsg = (uint32_t)(((kseg + bHf) ^ r7b) << 4);
                uint32_t bd0 = sB + boff0 + bsg;
                uint32_t bd1 = sB + boff1 + bsg;
                LDSM_X4(bh[0][0], bh[0][1], bh[0][2], bh[0][3], bd0);
                LDSM_X4(bh[1][0], bh[1][1], bh[1][2], bh[1][3], bd1);
                LDSM_X4(bl[0][0], bl[0][1], bl[0][2], bl[0][3], bd0 + 8192);
                LDSM_X4(bl[1][0], bl[1][1], bl[1][2], bl[1][3], bd1 + 8192);
            }
#pragma unroll
            for (int mt = 0; mt < 2; mt++)
#pragma unroll
                for (int p = 0; p < 2; p++)
#pragma unroll
                    for (int hf = 0; hf < 2; hf++) {
                        float* dd = d[mt][p * 2 + hf];
                        mma16816(dd, ah[mt], &bh[p][hf * 2]);
                        mma16816(dd, ah[mt], &bl[p][hf * 2]);
                        mma16816(dd, al[mt], &bh[p][hf * 2]);
                    }
        }
        __syncthreads();                       // all warps done reading stage s
        if (tid == 0 && it + NSTAGE < NIT) issue_stage(s, it + NSTAGE);
    }

    // epilogue: add biases, store fp32
#pragma unroll
    for (int mt = 0; mt < 2; mt++) {
#pragma unroll
        for (int nt = 0; nt < 4; nt++) {
            int rowm = mblk + warp_m * 32 + mt * 16 + (lane >> 2);
            int coln = nblk + warp_n * 32 + nt * 8 + (lane & 3) * 2;
            float bi0 = b_ih[coln]     + b_hh[coln];
            float bi1 = b_ih[coln + 1] + b_hh[coln + 1];
            float* p0 = g_gates + (size_t)rowm * GN + coln;
            float* p1 = g_gates + (size_t)(rowm + 8) * GN + coln;
            float2 v0 = {d[mt][nt][0] + bi0, d[mt][nt][1] + bi1};
            float2 v1 = {d[mt][nt][2] + bi0, d[mt][nt][3] + bi1};
            *(float2*)p0 = v0;
            *(float2*)p1 = v1;
        }
    }
}

// ---------------------------------------------------------------------------
// Kernel 3: LSTM recurrence
// ---------------------------------------------------------------------------
__global__ __launch_bounds__(1024) void lstm_kernel(const float* __restrict__ W_hh)
{
    __shared__ float hbuf[Hz];
    __shared__ float gbuf[G4];

    const int b   = blockIdx.x;
    const int tid = threadIdx.x;
    if (tid < Hz) hbuf[tid] = 0.f;
    float c = 0.f;

    const float4* wrow = (const float4*)(W_hh + (size_t)tid * Hz);
    const float*  pre  = g_gates + (size_t)b * Tz * G4;
    __syncthreads();

    for (int t = 0; t < Tz; t++) {
        float acc = pre[t * G4 + tid];
        const float4* hv = (const float4*)hbuf;
#pragma unroll 8
        for (int k = 0; k < Hz / 4; k++) {
            float4 w  = wrow[k];
            float4 h4 = hv[k];
            acc = fmaf(w.x, h4.x, acc);
            acc = fmaf(w.y, h4.y, acc);
            acc = fmaf(w.z, h4.z, acc);
            acc = fmaf(w.w, h4.w, acc);
        }
        gbuf[tid] = acc;
        __syncthreads();
        if (tid < Hz) {
            float gi = 1.f / (1.f + __expf(-gbuf[tid]));
            float gf = 1.f / (1.f + __expf(-gbuf[Hz + tid]));
            float gg = tanhf(gbuf[2 * Hz + tid]);
            float go = 1.f / (1.f + __expf(-gbuf[3 * Hz + tid]));
            c = gf * c + gi * gg;
            hbuf[tid] = go * tanhf(c);
        }
        __syncthreads();
    }
    if (tid < Hz) g_hlast[b * Hz + tid] = hbuf[tid];
}

// ---------------------------------------------------------------------------
// Kernel 4: output linear
// ---------------------------------------------------------------------------
__global__ __launch_bounds__(256) void out_kernel(
    const float* __restrict__ Wo, const float* __restrict__ bo,
    float* __restrict__ out)
{
    const int b = blockIdx.x, n = threadIdx.x;
    const float4* h4 = (const float4*)(g_hlast + b * Hz);
    const float4* w4 = (const float4*)(Wo + n * Hz);
    float acc = bo[n];
#pragma unroll 8
    for (int k = 0; k < Hz / 4; k++) {
        float4 w = w4[k], h = h4[k];
        acc = fmaf(w.x, h.x, acc);
        acc = fmaf(w.y, h.y, acc);
        acc = fmaf(w.z, h.z, acc);
        acc = fmaf(w.w, h.w, acc);
    }
    out[b * Nz + n] = acc;
}

// ---------------------------------------------------------------------------
extern "C" void kernel_launch(void* const* d_in, const int* in_sizes, int n_in,
                              void* d_out, int out_size)
{
    const float* x     = (const float*)d_in[0];
    const float* adj   = (const float*)d_in[1];
    const float* W     = (const float*)d_in[2];
    const float* a_src = (const float*)d_in[3];
    const float* a_dst = (const float*)d_in[4];
    const float* gat_b = (const float*)d_in[5];
    const float* W_ih  = (const float*)d_in[6];
    const float* W_hh  = (const float*)d_in[7];
    const float* b_ih  = (const float*)d_in[8];
    const float* b_hh  = (const float*)d_in[9];
    const float* Wo    = (const float*)d_in[10];
    const float* bo    = (const float*)d_in[11];
    float* out = (float*)d_out;

    cudaFuncSetAttribute(tc_gemm_kernel,
                         cudaFuncAttributeMaxDynamicSharedMemorySize, SMEM_DYN);

    conv_wih_kernel<<<(int)(((size_t)GN * GK / 8) / 256), 256>>>(W_ih);
    gat_kernel<<<GM, 256>>>(x, adj, W, a_src, a_dst, gat_b);

    dim3 gg(GN / BN, GM / BM);   // 16 x 8 = 128 CTAs
    tc_gemm_kernel<<<gg, 256, SMEM_DYN>>>(b_ih, b_hh);

    lstm_kernel<<<Bz, 1024>>>(W_hh);

    out_kernel<<<Bz, 256>>>(Wo, bo, out);
}

// round 5
// speedup vs baseline: 1.3918x; 1.0752x over previous
#include <cuda_runtime.h>
#include <cuda_bf16.h>
#include <math.h>
#include <stdint.h>

// Problem dims
#define Bz   32
#define Tz   32
#define Nz   256
#define FIN  32
#define FOUT 32
#define Hz   256
#define INz  8192
#define G4   1024
#define GM   1024   // Bz*Tz rows of seq
#define GK   8192
#define GN   1024

// GEMM tiling
#define BM 128
#define BN 64
#define BK 64
#define NIT (GK / BK)          // 128
#define NSTAGE 3
#define OFF_AL 16384
#define OFF_BH 32768
#define OFF_BL 40960
#define STAGE_B 49152          // Ah16K + Al16K + Bh8K + Bl8K
#define SMEM_DYN (NSTAGE * STAGE_B)   // 144 KB

// ---------------------------------------------------------------------------
// Scratch (static device globals). seq/wih stored in ldmatrix-swizzled tiled
// layout: offset = ((rowtile*128 + kchunk) << 14) + row*128 + ((seg^(row&7))<<4) + (k&7)*2
// ---------------------------------------------------------------------------
__device__ __align__(128) __nv_bfloat16 g_seq_hi[(size_t)GM * GK];
__device__ __align__(128) __nv_bfloat16 g_seq_lo[(size_t)GM * GK];
__device__ __align__(128) __nv_bfloat16 g_wih_hi[(size_t)GN * GK];
__device__ __align__(128) __nv_bfloat16 g_wih_lo[(size_t)GN * GK];
__device__ float g_gates[(size_t)GM * G4];
__device__ float g_hlast[Bz * Hz];

// ---------------------------------------------------------------------------
// PTX helpers (baseline features only — nothing 'a'-suffix)
// ---------------------------------------------------------------------------
__device__ __forceinline__ uint32_t smem_u32(const void* p) {
    return (uint32_t)__cvta_generic_to_shared(p);
}

#define MBARRIER_INIT(addr, cnt) \
    asm volatile("mbarrier.init.shared.b64 [%0], %1;" :: "r"(addr), "r"(cnt) : "memory")
#define MBARRIER_EXPECT_TX(addr, bytes) \
    asm volatile("mbarrier.arrive.expect_tx.shared.b64 _, [%0], %1;" :: "r"(addr), "r"(bytes) : "memory")
#define MBARRIER_WAIT_PARITY(addr, par) do {                                        \
    uint32_t _mbar = (addr); uint32_t _p = (par); uint32_t _done;                   \
    asm volatile("{\n\t.reg .pred p;\n\t"                                           \
        "mbarrier.try_wait.parity.acquire.cta.shared::cta.b64 p, [%1], %2;\n\t"     \
        "selp.b32 %0, 1, 0, p;\n\t}"                                                \
        : "=r"(_done) : "r"(_mbar), "r"(_p) : "memory");                            \
    if (!_done) {                                                                   \
        asm volatile("{\n\t.reg .pred P1;\n\t"                                      \
            "WAIT_LOOP_%=:\n\t"                                                     \
            "mbarrier.try_wait.parity.acquire.cta.shared::cta.b64 P1, [%0], %1, 0x989680;\n\t" \
            "@P1 bra.uni WAIT_DONE_%=;\n\t"                                         \
            "bra.uni WAIT_LOOP_%=;\n\t"                                             \
            "WAIT_DONE_%=:\n\t}"                                                    \
            :: "r"(_mbar), "r"(_p) : "memory");                                     \
    } } while (0)

#define BULK_G2S(dst, src, bytes, mbar) \
    asm volatile("cp.async.bulk.shared::cluster.global.mbarrier::complete_tx::bytes [%0], [%1], %2, [%3];" \
        :: "r"(dst), "l"(src), "r"(bytes), "r"(mbar) : "memory")

#define FENCE_ASYNC() asm volatile("fence.proxy.async.shared::cta;" ::: "memory")

#define LDSM_X4(r0, r1, r2, r3, addr) \
    asm volatile("ldmatrix.sync.aligned.m8n8.x4.shared.b16 {%0,%1,%2,%3}, [%4];" \
        : "=r"(r0), "=r"(r1), "=r"(r2), "=r"(r3) : "r"(addr))

__device__ __forceinline__ void mma16816(float* d, const uint32_t* a, const uint32_t* b) {
    asm volatile(
        "mma.sync.aligned.m16n8k16.row.col.f32.bf16.bf16.f32 "
        "{%0,%1,%2,%3}, {%4,%5,%6,%7}, {%8,%9}, {%0,%1,%2,%3};"
        : "+f"(d[0]), "+f"(d[1]), "+f"(d[2]), "+f"(d[3])
        : "r"(a[0]), "r"(a[1]), "r"(a[2]), "r"(a[3]), "r"(b[0]), "r"(b[1]));
}

__device__ __forceinline__ uint32_t pack_bf16x2(float v0, float v1) {
    unsigned short a = __bfloat16_as_ushort(__float2bfloat16(v0));
    unsigned short b = __bfloat16_as_ushort(__float2bfloat16(v1));
    return ((uint32_t)b << 16) | a;
}
__device__ __forceinline__ void split_bf16(float v, float& hi, float& lo) {
    __nv_bfloat16 h = __float2bfloat16(v);
    hi = __bfloat162float(h);
    lo = v - hi;
}

// ---------------------------------------------------------------------------
// Kernel 1: GAT per (b,t). Chunked aggregation: batch 16 adj loads (branch-
// free, ALU select) -> MLP=16, then unconditional FMA sweep.
// ---------------------------------------------------------------------------
__global__ __launch_bounds__(256) void gat_kernel(
    const float* __restrict__ x, const float* __restrict__ adj,
    const float* __restrict__ W, const float* __restrict__ a_src,
    const float* __restrict__ a_dst, const float* __restrict__ gat_b)
{
    __shared__ float sh[Nz][36];
    __shared__ float ssrc[Nz];
    __shared__ float sW[FIN][FOUT];
    __shared__ float sas[FOUT], sad[FOUT], sbias[FOUT];

    const int bt  = blockIdx.x;
    const int tid = threadIdx.x;
    const float* xb   = x   + (size_t)bt * Nz * FIN;
    const float* adjb = adj + (size_t)bt * Nz * Nz;

    for (int i = tid; i < FIN * FOUT; i += 256) sW[i / FOUT][i % FOUT] = W[i];
    if (tid < FOUT) { sas[tid] = a_src[tid]; sad[tid] = a_dst[tid]; sbias[tid] = gat_b[tid]; }
    __syncthreads();

    float xv[FIN];
#pragma unroll
    for (int k = 0; k < FIN; k++) xv[k] = xb[tid * FIN + k];
    float vsrc = 0.f, vdst = 0.f;
#pragma unroll
    for (int o = 0; o < FOUT; o++) {
        float acc = 0.f;
#pragma unroll
        for (int k = 0; k < FIN; k++) acc = fmaf(xv[k], sW[k][o], acc);
        sh[tid][o] = acc;
        vsrc = fmaf(acc, sas[o], vsrc);
        vdst = fmaf(acc, sad[o], vdst);
    }
    ssrc[tid] = vsrc;
    __syncthreads();

    float l = 0.f;
    float acc[FOUT];
#pragma unroll
    for (int o = 0; o < FOUT; o++) acc[o] = 0.f;

    for (int c = 0; c < Nz; c += 16) {
        // phase A: 16 batched adj loads + branch-free p computation
        float p[16];
#pragma unroll
        for (int jj = 0; jj < 16; jj++) {
            float av = adjb[(size_t)(c + jj) * Nz + tid];
            float e = vdst + ssrc[c + jj];
            e = (e > 0.f) ? e : 0.2f * e;
            float pe = __expf(e);
            bool edge = (av != 0.f) | ((c + jj) == tid);
            p[jj] = edge ? pe : 0.f;
            l += p[jj];
        }
        // phase B: unconditional weighted accumulation from smem
#pragma unroll
        for (int jj = 0; jj < 16; jj++) {
            float pj = p[jj];
            const float4* hj = (const float4*)&sh[c + jj][0];
#pragma unroll
            for (int q = 0; q < 8; q++) {
                float4 hv = hj[q];
                acc[4*q+0] = fmaf(pj, hv.x, acc[4*q+0]);
                acc[4*q+1] = fmaf(pj, hv.y, acc[4*q+1]);
                acc[4*q+2] = fmaf(pj, hv.z, acc[4*q+2]);
                acc[4*q+3] = fmaf(pj, hv.w, acc[4*q+3]);
            }
        }
    }

    float inv = 1.f / l;   // l > 0 always (self loop)
    float vh[FOUT], vl[FOUT];
#pragma unroll
    for (int o = 0; o < FOUT; o++) {
        float v = fmaf(acc[o], inv, sbias[o]);
        split_bf16(v, vh[o], vl[o]);
    }

    // write swizzled tiled layout: row m = bt, k = tid*32 + (g*8 + e)
    const int mtile = bt >> 7, mrow = bt & 127;
    const int chunk = tid >> 1;
    const int seg0  = (tid & 1) * 4;
    unsigned char* baseh = (unsigned char*)g_seq_hi + (((size_t)(mtile * 128 + chunk)) << 14) + mrow * 128;
    unsigned char* basel = (unsigned char*)g_seq_lo + (((size_t)(mtile * 128 + chunk)) << 14) + mrow * 128;
#pragma unroll
    for (int g = 0; g < 4; g++) {
        uint32_t sw = (uint32_t)(((seg0 + g) ^ (mrow & 7)) << 4);
        uint4 uh, ul;
        uh.x = pack_bf16x2(vh[g*8+0], vh[g*8+1]);
        uh.y = pack_bf16x2(vh[g*8+2], vh[g*8+3]);
        uh.z = pack_bf16x2(vh[g*8+4], vh[g*8+5]);
        uh.w = pack_bf16x2(vh[g*8+6], vh[g*8+7]);
        ul.x = pack_bf16x2(vl[g*8+0], vl[g*8+1]);
        ul.y = pack_bf16x2(vl[g*8+2], vl[g*8+3]);
        ul.z = pack_bf16x2(vl[g*8+4], vl[g*8+5]);
        ul.w = pack_bf16x2(vl[g*8+6], vl[g*8+7]);
        *(uint4*)(baseh + sw) = uh;
        *(uint4*)(basel + sw) = ul;
    }
}

// ---------------------------------------------------------------------------
// Kernel 1b: W_ih fp32 -> swizzled tiled bf16 hi/lo
// ---------------------------------------------------------------------------
__global__ __launch_bounds__(256) void conv_wih_kernel(const float* __restrict__ W_ih)
{
    size_t t = (size_t)blockIdx.x * 256 + threadIdx.x;
    int n = (int)(t >> 10);
    int s = (int)(t & 1023);
    int k0 = s * 8;
    const float* src = W_ih + (size_t)n * GK + k0;
    float4 v0 = *(const float4*)(src);
    float4 v1 = *(const float4*)(src + 4);
    float f[8] = {v0.x, v0.y, v0.z, v0.w, v1.x, v1.y, v1.z, v1.w};
    float fh[8], fl[8];
#pragma unroll
    for (int i = 0; i < 8; i++) split_bf16(f[i], fh[i], fl[i]);

    int ntile = n >> 7, nrow = n & 127, chunk = s >> 3, seg = s & 7;
    size_t off = (((size_t)(ntile * 128 + chunk)) << 14) + nrow * 128
               + (uint32_t)((seg ^ (nrow & 7)) << 4);
    uint4 uh, ul;
    uh.x = pack_bf16x2(fh[0], fh[1]); uh.y = pack_bf16x2(fh[2], fh[3]);
    uh.z = pack_bf16x2(fh[4], fh[5]); uh.w = pack_bf16x2(fh[6], fh[7]);
    ul.x = pack_bf16x2(fl[0], fl[1]); ul.y = pack_bf16x2(fl[2], fl[3]);
    ul.z = pack_bf16x2(fl[4], fl[5]); ul.w = pack_bf16x2(fl[6], fl[7]);
    *(uint4*)((unsigned char*)g_wih_hi + off) = uh;
    *(uint4*)((unsigned char*)g_wih_lo + off) = ul;
}

// ---------------------------------------------------------------------------
// Kernel 2: split-bf16 mma.sync GEMM fed by cp.async.bulk + mbarrier.
// ---------------------------------------------------------------------------
__global__ __launch_bounds__(256) void tc_gemm_kernel(
    const float* __restrict__ b_ih, const float* __restrict__ b_hh)
{
    extern __shared__ __align__(128) unsigned char dsmem[];
    __shared__ __align__(8) unsigned long long s_full[NSTAGE];
    const uint32_t dsm = smem_u32(dsmem);

    const int tid  = threadIdx.x;
    const int lane = tid & 31;
    const int wid  = tid >> 5;
    const int warp_m = wid >> 1;
    const int warp_n = wid & 1;
    const int mblk = blockIdx.y * BM;
    const int nblk = blockIdx.x * BN;
    const int mtile = blockIdx.y;
    const int ntile = blockIdx.x >> 1;
    const size_t bhalf = (size_t)(blockIdx.x & 1) * 8192;

    if (tid == 0) {
        for (int p = 0; p < NSTAGE; p++) MBARRIER_INIT(smem_u32(&s_full[p]), 1);
        FENCE_ASYNC();
    }
    __syncthreads();

    const unsigned char* srcAh = (const unsigned char*)g_seq_hi + (((size_t)mtile * 128) << 14);
    const unsigned char* srcAl = (const unsigned char*)g_seq_lo + (((size_t)mtile * 128) << 14);
    const unsigned char* srcBh = (const unsigned char*)g_wih_hi + (((size_t)ntile * 128) << 14) + bhalf;
    const unsigned char* srcBl = (const unsigned char*)g_wih_lo + (((size_t)ntile * 128) << 14) + bhalf;

    auto issue_stage = [&](int st, int it) {
        uint32_t sb = dsm + st * STAGE_B;
        uint32_t fb = smem_u32(&s_full[st]);
        size_t off = (size_t)it << 14;
        MBARRIER_EXPECT_TX(fb, STAGE_B);
        BULK_G2S(sb,          srcAh + off, 16384, fb);
        BULK_G2S(sb + OFF_AL, srcAl + off, 16384, fb);
        BULK_G2S(sb + OFF_BH, srcBh + off,  8192, fb);
        BULK_G2S(sb + OFF_BL, srcBl + off,  8192, fb);
    };

    if (tid == 0) {
        issue_stage(0, 0);
        issue_stage(1, 1);
        issue_stage(2, 2);
    }

    const int rA  = warp_m * 32 + (lane & 7) + ((lane >> 3) & 1) * 8;
    const int aHf = lane >> 4;
    const int r7a = rA & 7;
    const int rB  = warp_n * 32 + (lane & 7) + ((lane >> 4) & 1) * 8;
    const int bHf = (lane >> 3) & 1;
    const int r7b = rB & 7;
    const uint32_t aoff0 = (uint32_t)rA * 128;
    const uint32_t aoff1 = aoff0 + 16 * 128;
    const uint32_t boff0 = (uint32_t)rB * 128;
    const uint32_t boff1 = boff0 + 16 * 128;

    float d[2][4][4];
#pragma unroll
    for (int i = 0; i < 2; i++)
#pragma unroll
        for (int j = 0; j < 4; j++)
#pragma unroll
            for (int q = 0; q < 4; q++) d[i][j][q] = 0.f;

    for (int it = 0; it < NIT; it++) {
        int s = it % NSTAGE;
        MBARRIER_WAIT_PARITY(smem_u32(&s_full[s]), (it / NSTAGE) & 1);

        uint32_t sA = dsm + s * STAGE_B;
        uint32_t sB = sA + OFF_BH;
#pragma unroll
        for (int ks = 0; ks < 4; ks++) {
            int kseg = ks * 2;
            uint32_t ah[2][4], al[2][4], bh[2][4], bl[2][4];
            {
                uint32_t asg = (uint32_t)(((kseg + aHf) ^ r7a) << 4);
                uint32_t ad0 = sA + aoff0 + asg;
                uint32_t ad1 = sA + aoff1 + asg;
                LDSM_X4(ah[0][0], ah[0][1], ah[0][2], ah[0][3], ad0);
                LDSM_X4(ah[1][0], ah[1][1], ah[1][2], ah[1][3], ad1);
                LDSM_X4(al[0][0], al[0][1], al[0][2], al[0][3], ad0 + OFF_AL);
                LDSM_X4(al[1][0], al[1][1], al[1][2], al[1][3], ad1 + OFF_AL);
            }
            {
                uint32_t bsg = (uint32_t)(((kseg + bHf) ^ r7b) << 4);
                uint32_t bd0 = sB + boff0 + bsg;
                uint32_t bd1 = sB + boff1 + bsg;
                LDSM_X4(bh[0][0], bh[0][1], bh[0][2], bh[0][3], bd0);
                LDSM_X4(bh[1][0], bh[1][1], bh[1][2], bh[1][3], bd1);
                LDSM_X4(bl[0][0], bl[0][1], bl[0][2], bl[0][3], bd0 + 8192);
                LDSM_X4(bl[1][0], bl[1][1], bl[1][2], bl[1][3], bd1 + 8192);
            }
#pragma unroll
            for (int mt = 0; mt < 2; mt++)
#pragma unroll
                for (int p = 0; p < 2; p++)
#pragma unroll
                    for (int hf = 0; hf < 2; hf++) {
                        float* dd = d[mt][p * 2 + hf];
                        mma16816(dd, ah[mt], &bh[p][hf * 2]);
                        mma16816(dd, ah[mt], &bl[p][hf * 2]);
                        mma16816(dd, al[mt], &bh[p][hf * 2]);
                    }
        }
        __syncthreads();
        if (tid == 0 && it + NSTAGE < NIT) issue_stage(s, it + NSTAGE);
    }

    // epilogue
#pragma unroll
    for (int mt = 0; mt < 2; mt++) {
#pragma unroll
        for (int nt = 0; nt < 4; nt++) {
            int rowm = mblk + warp_m * 32 + mt * 16 + (lane >> 2);
            int coln = nblk + warp_n * 32 + nt * 8 + (lane & 3) * 2;
            float bi0 = b_ih[coln]     + b_hh[coln];
            float bi1 = b_ih[coln + 1] + b_hh[coln + 1];
            float* p0 = g_gates + (size_t)rowm * GN + coln;
            float* p1 = g_gates + (size_t)(rowm + 8) * GN + coln;
            float2 v0 = {d[mt][nt][0] + bi0, d[mt][nt][1] + bi1};
            float2 v1 = {d[mt][nt][2] + bi0, d[mt][nt][3] + bi1};
            *(float2*)p0 = v0;
            *(float2*)p1 = v1;
        }
    }
}

// ---------------------------------------------------------------------------
// Kernel 3: LSTM recurrence
// ---------------------------------------------------------------------------
__global__ __launch_bounds__(1024) void lstm_kernel(const float* __restrict__ W_hh)
{
    __shared__ float hbuf[Hz];
    __shared__ float gbuf[G4];

    const int b   = blockIdx.x;
    const int tid = threadIdx.x;
    if (tid < Hz) hbuf[tid] = 0.f;
    float c = 0.f;

    const float4* wrow = (const float4*)(W_hh + (size_t)tid * Hz);
    const float*  pre  = g_gates + (size_t)b * Tz * G4;
    __syncthreads();

    for (int t = 0; t < Tz; t++) {
        float acc = pre[t * G4 + tid];
        const float4* hv = (const float4*)hbuf;
#pragma unroll 8
        for (int k = 0; k < Hz / 4; k++) {
            float4 w  = wrow[k];
            float4 h4 = hv[k];
            acc = fmaf(w.x, h4.x, acc);
            acc = fmaf(w.y, h4.y, acc);
            acc = fmaf(w.z, h4.z, acc);
            acc = fmaf(w.w, h4.w, acc);
        }
        gbuf[tid] = acc;
        __syncthreads();
        if (tid < Hz) {
            float gi = 1.f / (1.f + __expf(-gbuf[tid]));
            float gf = 1.f / (1.f + __expf(-gbuf[Hz + tid]));
            float gg = tanhf(gbuf[2 * Hz + tid]);
            float go = 1.f / (1.f + __expf(-gbuf[3 * Hz + tid]));
            c = gf * c + gi * gg;
            hbuf[tid] = go * tanhf(c);
        }
        __syncthreads();
    }
    if (tid < Hz) g_hlast[b * Hz + tid] = hbuf[tid];
}

// ---------------------------------------------------------------------------
// Kernel 4: output linear
// ---------------------------------------------------------------------------
__global__ __launch_bounds__(256) void out_kernel(
    const float* __restrict__ Wo, const float* __restrict__ bo,
    float* __restrict__ out)
{
    const int b = blockIdx.x, n = threadIdx.x;
    const float4* h4 = (const float4*)(g_hlast + b * Hz);
    const float4* w4 = (const float4*)(Wo + n * Hz);
    float acc = bo[n];
#pragma unroll 8
    for (int k = 0; k < Hz / 4; k++) {
        float4 w = w4[k], h = h4[k];
        acc = fmaf(w.x, h.x, acc);
        acc = fmaf(w.y, h.y, acc);
        acc = fmaf(w.z, h.z, acc);
        acc = fmaf(w.w, h.w, acc);
    }
    out[b * Nz + n] = acc;
}

// ---------------------------------------------------------------------------
extern "C" void kernel_launch(void* const* d_in, const int* in_sizes, int n_in,
                              void* d_out, int out_size)
{
    const float* x     = (const float*)d_in[0];
    const float* adj   = (const float*)d_in[1];
    const float* W     = (const float*)d_in[2];
    const float* a_src = (const float*)d_in[3];
    const float* a_dst = (const float*)d_in[4];
    const float* gat_b = (const float*)d_in[5];
    const float* W_ih  = (const float*)d_in[6];
    const float* W_hh  = (const float*)d_in[7];
    const float* b_ih  = (const float*)d_in[8];
    const float* b_hh  = (const float*)d_in[9];
    const float* Wo    = (const float*)d_in[10];
    const float* bo    = (const float*)d_in[11];
    float* out = (float*)d_out;

    cudaFuncSetAttribute(tc_gemm_kernel,
                         cudaFuncAttributeMaxDynamicSharedMemorySize, SMEM_DYN);

    conv_wih_kernel<<<(int)(((size_t)GN * GK / 8) / 256), 256>>>(W_ih);
    gat_kernel<<<GM, 256>>>(x, adj, W, a_src, a_dst, gat_b);

    dim3 gg(GN / BN, GM / BM);   // 16 x 8 = 128 CTAs
    tc_gemm_kernel<<<gg, 256, SMEM_DYN>>>(b_ih, b_hh);

    lstm_kernel<<<Bz, 1024>>>(W_hh);

    out_kernel<<<Bz, 256>>>(Wo, bo, out);
}

// round 6
// speedup vs baseline: 2.2117x; 1.5891x over previous
#include <cuda_runtime.h>
#include <cuda_bf16.h>
#include <math.h>
#include <stdint.h>

// Problem dims
#define Bz   32
#define Tz   32
#define Nz   256
#define FIN  32
#define FOUT 32
#define Hz   256
#define INz  8192
#define G4   1024
#define GM   1024   // Bz*Tz rows of seq
#define GK   8192
#define GN   1024

// GEMM tiling
#define BM 128
#define BN 64
#define BK 64
#define NIT (GK / BK)          // 128
#define NSTAGE 3
#define OFF_AL 16384
#define OFF_BH 32768
#define OFF_BL 40960
#define STAGE_B 49152          // Ah16K + Al16K + Bh8K + Bl8K
#define SMEM_DYN (NSTAGE * STAGE_B)   // 144 KB

// ---------------------------------------------------------------------------
// Scratch (static device globals). seq/wih stored in ldmatrix-swizzled tiled
// layout: offset = ((rowtile*128 + kchunk) << 14) + row*128 + ((seg^(row&7))<<4) + (k&7)*2
// ---------------------------------------------------------------------------
__device__ __align__(128) __nv_bfloat16 g_seq_hi[(size_t)GM * GK];
__device__ __align__(128) __nv_bfloat16 g_seq_lo[(size_t)GM * GK];
__device__ __align__(128) __nv_bfloat16 g_wih_hi[(size_t)GN * GK];
__device__ __align__(128) __nv_bfloat16 g_wih_lo[(size_t)GN * GK];
__device__ float g_gates[(size_t)GM * G4];
__device__ float4 g_whhT[(Hz / 4) * G4];    // packed transpose: [k/4][g] -> 4 k-values
__device__ float g_hlast[Bz * Hz];

// ---------------------------------------------------------------------------
// PTX helpers (baseline features only — nothing 'a'-suffix)
// ---------------------------------------------------------------------------
__device__ __forceinline__ uint32_t smem_u32(const void* p) {
    return (uint32_t)__cvta_generic_to_shared(p);
}

#define MBARRIER_INIT(addr, cnt) \
    asm volatile("mbarrier.init.shared.b64 [%0], %1;" :: "r"(addr), "r"(cnt) : "memory")
#define MBARRIER_EXPECT_TX(addr, bytes) \
    asm volatile("mbarrier.arrive.expect_tx.shared.b64 _, [%0], %1;" :: "r"(addr), "r"(bytes) : "memory")
#define MBARRIER_WAIT_PARITY(addr, par) do {                                        \
    uint32_t _mbar = (addr); uint32_t _p = (par); uint32_t _done;                   \
    asm volatile("{\n\t.reg .pred p;\n\t"                                           \
        "mbarrier.try_wait.parity.acquire.cta.shared::cta.b64 p, [%1], %2;\n\t"     \
        "selp.b32 %0, 1, 0, p;\n\t}"                                                \
        : "=r"(_done) : "r"(_mbar), "r"(_p) : "memory");                            \
    if (!_done) {                                                                   \
        asm volatile("{\n\t.reg .pred P1;\n\t"                                      \
            "WAIT_LOOP_%=:\n\t"                                                     \
            "mbarrier.try_wait.parity.acquire.cta.shared::cta.b64 P1, [%0], %1, 0x989680;\n\t" \
            "@P1 bra.uni WAIT_DONE_%=;\n\t"                                         \
            "bra.uni WAIT_LOOP_%=;\n\t"                                             \
            "WAIT_DONE_%=:\n\t}"                                                    \
            :: "r"(_mbar), "r"(_p) : "memory");                                     \
    } } while (0)

#define BULK_G2S(dst, src, bytes, mbar) \
    asm volatile("cp.async.bulk.shared::cluster.global.mbarrier::complete_tx::bytes [%0], [%1], %2, [%3];" \
        :: "r"(dst), "l"(src), "r"(bytes), "r"(mbar) : "memory")

#define FENCE_ASYNC() asm volatile("fence.proxy.async.shared::cta;" ::: "memory")

#define LDSM_X4(r0, r1, r2, r3, addr) \
    asm volatile("ldmatrix.sync.aligned.m8n8.x4.shared.b16 {%0,%1,%2,%3}, [%4];" \
        : "=r"(r0), "=r"(r1), "=r"(r2), "=r"(r3) : "r"(addr))

__device__ __forceinline__ void mma16816(float* d, const uint32_t* a, const uint32_t* b) {
    asm volatile(
        "mma.sync.aligned.m16n8k16.row.col.f32.bf16.bf16.f32 "
        "{%0,%1,%2,%3}, {%4,%5,%6,%7}, {%8,%9}, {%0,%1,%2,%3};"
        : "+f"(d[0]), "+f"(d[1]), "+f"(d[2]), "+f"(d[3])
        : "r"(a[0]), "r"(a[1]), "r"(a[2]), "r"(a[3]), "r"(b[0]), "r"(b[1]));
}

__device__ __forceinline__ uint32_t pack_bf16x2(float v0, float v1) {
    unsigned short a = __bfloat16_as_ushort(__float2bfloat16(v0));
    unsigned short b = __bfloat16_as_ushort(__float2bfloat16(v1));
    return ((uint32_t)b << 16) | a;
}
__device__ __forceinline__ void split_bf16(float v, float& hi, float& lo) {
    __nv_bfloat16 h = __float2bfloat16(v);
    hi = __bfloat162float(h);
    lo = v - hi;
}

// ---------------------------------------------------------------------------
// Kernel 1: GAT per (b,t). Chunked: 16 batched adj loads -> MLP=16, then
// unconditional FMA sweep.
// ---------------------------------------------------------------------------
__global__ __launch_bounds__(256) void gat_kernel(
    const float* __restrict__ x, const float* __restrict__ adj,
    const float* __restrict__ W, const float* __restrict__ a_src,
    const float* __restrict__ a_dst, const float* __restrict__ gat_b)
{
    __shared__ float sh[Nz][36];
    __shared__ float ssrc[Nz];
    __shared__ float sW[FIN][FOUT];
    __shared__ float sas[FOUT], sad[FOUT], sbias[FOUT];

    const int bt  = blockIdx.x;
    const int tid = threadIdx.x;
    const float* xb   = x   + (size_t)bt * Nz * FIN;
    const float* adjb = adj + (size_t)bt * Nz * Nz;

    for (int i = tid; i < FIN * FOUT; i += 256) sW[i / FOUT][i % FOUT] = W[i];
    if (tid < FOUT) { sas[tid] = a_src[tid]; sad[tid] = a_dst[tid]; sbias[tid] = gat_b[tid]; }
    __syncthreads();

    float xv[FIN];
#pragma unroll
    for (int k = 0; k < FIN; k++) xv[k] = xb[tid * FIN + k];
    float vsrc = 0.f, vdst = 0.f;
#pragma unroll
    for (int o = 0; o < FOUT; o++) {
        float acc = 0.f;
#pragma unroll
        for (int k = 0; k < FIN; k++) acc = fmaf(xv[k], sW[k][o], acc);
        sh[tid][o] = acc;
        vsrc = fmaf(acc, sas[o], vsrc);
        vdst = fmaf(acc, sad[o], vdst);
    }
    ssrc[tid] = vsrc;
    __syncthreads();

    float l = 0.f;
    float acc[FOUT];
#pragma unroll
    for (int o = 0; o < FOUT; o++) acc[o] = 0.f;

    for (int c = 0; c < Nz; c += 16) {
        float p[16];
#pragma unroll
        for (int jj = 0; jj < 16; jj++) {
            float av = adjb[(size_t)(c + jj) * Nz + tid];
            float e = vdst + ssrc[c + jj];
            e = (e > 0.f) ? e : 0.2f * e;
            float pe = __expf(e);
            bool edge = (av != 0.f) | ((c + jj) == tid);
            p[jj] = edge ? pe : 0.f;
            l += p[jj];
        }
#pragma unroll
        for (int jj = 0; jj < 16; jj++) {
            float pj = p[jj];
            const float4* hj = (const float4*)&sh[c + jj][0];
#pragma unroll
            for (int q = 0; q < 8; q++) {
                float4 hv = hj[q];
                acc[4*q+0] = fmaf(pj, hv.x, acc[4*q+0]);
                acc[4*q+1] = fmaf(pj, hv.y, acc[4*q+1]);
                acc[4*q+2] = fmaf(pj, hv.z, acc[4*q+2]);
                acc[4*q+3] = fmaf(pj, hv.w, acc[4*q+3]);
            }
        }
    }

    float inv = 1.f / l;
    float vh[FOUT], vl[FOUT];
#pragma unroll
    for (int o = 0; o < FOUT; o++) {
        float v = fmaf(acc[o], inv, sbias[o]);
        split_bf16(v, vh[o], vl[o]);
    }

    const int mtile = bt >> 7, mrow = bt & 127;
    const int chunk = tid >> 1;
    const int seg0  = (tid & 1) * 4;
    unsigned char* baseh = (unsigned char*)g_seq_hi + (((size_t)(mtile * 128 + chunk)) << 14) + mrow * 128;
    unsigned char* basel = (unsigned char*)g_seq_lo + (((size_t)(mtile * 128 + chunk)) << 14) + mrow * 128;
#pragma unroll
    for (int g = 0; g < 4; g++) {
        uint32_t sw = (uint32_t)(((seg0 + g) ^ (mrow & 7)) << 4);
        uint4 uh, ul;
        uh.x = pack_bf16x2(vh[g*8+0], vh[g*8+1]);
        uh.y = pack_bf16x2(vh[g*8+2], vh[g*8+3]);
        uh.z = pack_bf16x2(vh[g*8+4], vh[g*8+5]);
        uh.w = pack_bf16x2(vh[g*8+6], vh[g*8+7]);
        ul.x = pack_bf16x2(vl[g*8+0], vl[g*8+1]);
        ul.y = pack_bf16x2(vl[g*8+2], vl[g*8+3]);
        ul.z = pack_bf16x2(vl[g*8+4], vl[g*8+5]);
        ul.w = pack_bf16x2(vl[g*8+6], vl[g*8+7]);
        *(uint4*)(baseh + sw) = uh;
        *(uint4*)(basel + sw) = ul;
    }
}

// ---------------------------------------------------------------------------
// Kernel 1b: W_ih fp32 -> swizzled tiled bf16 hi/lo
// ---------------------------------------------------------------------------
__global__ __launch_bounds__(256) void conv_wih_kernel(const float* __restrict__ W_ih)
{
    size_t t = (size_t)blockIdx.x * 256 + threadIdx.x;
    int n = (int)(t >> 10);
    int s = (int)(t & 1023);
    int k0 = s * 8;
    const float* src = W_ih + (size_t)n * GK + k0;
    float4 v0 = *(const float4*)(src);
    float4 v1 = *(const float4*)(src + 4);
    float f[8] = {v0.x, v0.y, v0.z, v0.w, v1.x, v1.y, v1.z, v1.w};
    float fh[8], fl[8];
#pragma unroll
    for (int i = 0; i < 8; i++) split_bf16(f[i], fh[i], fl[i]);

    int ntile = n >> 7, nrow = n & 127, chunk = s >> 3, seg = s & 7;
    size_t off = (((size_t)(ntile * 128 + chunk)) << 14) + nrow * 128
               + (uint32_t)((seg ^ (nrow & 7)) << 4);
    uint4 uh, ul;
    uh.x = pack_bf16x2(fh[0], fh[1]); uh.y = pack_bf16x2(fh[2], fh[3]);
    uh.z = pack_bf16x2(fh[4], fh[5]); uh.w = pack_bf16x2(fh[6], fh[7]);
    ul.x = pack_bf16x2(fl[0], fl[1]); ul.y = pack_bf16x2(fl[2], fl[3]);
    ul.z = pack_bf16x2(fl[4], fl[5]); ul.w = pack_bf16x2(fl[6], fl[7]);
    *(uint4*)((unsigned char*)g_wih_hi + off) = uh;
    *(uint4*)((unsigned char*)g_wih_lo + off) = ul;
}

// ---------------------------------------------------------------------------
// Kernel 1c: W_hh [G4][Hz] -> packed transpose g_whhT[k/4][g] (float4 of 4 k's)
// One-time 1MB shuffle so the LSTM loads are lane-coalesced.
// ---------------------------------------------------------------------------
__global__ __launch_bounds__(256) void conv_whh_kernel(const float* __restrict__ W_hh)
{
    int t = blockIdx.x * 256 + threadIdx.x;   // 0..65535
    int g  = t & 1023;                        // gate row
    int k4 = t >> 10;                         // 0..63
    float4 v = *(const float4*)(W_hh + (size_t)g * Hz + k4 * 4);
    g_whhT[k4 * G4 + g] = v;
}

// ---------------------------------------------------------------------------
// Kernel 2: split-bf16 mma.sync GEMM fed by cp.async.bulk + mbarrier.
// ---------------------------------------------------------------------------
__global__ __launch_bounds__(256) void tc_gemm_kernel(
    const float* __restrict__ b_ih, const float* __restrict__ b_hh)
{
    extern __shared__ __align__(128) unsigned char dsmem[];
    __shared__ __align__(8) unsigned long long s_full[NSTAGE];
    const uint32_t dsm = smem_u32(dsmem);

    const int tid  = threadIdx.x;
    const int lane = tid & 31;
    const int wid  = tid >> 5;
    const int warp_m = wid >> 1;
    const int warp_n = wid & 1;
    const int mblk = blockIdx.y * BM;
    const int nblk = blockIdx.x * BN;
    const int mtile = blockIdx.y;
    const int ntile = blockIdx.x >> 1;
    const size_t bhalf = (size_t)(blockIdx.x & 1) * 8192;

    if (tid == 0) {
        for (int p = 0; p < NSTAGE; p++) MBARRIER_INIT(smem_u32(&s_full[p]), 1);
        FENCE_ASYNC();
    }
    __syncthreads();

    const unsigned char* srcAh = (const unsigned char*)g_seq_hi + (((size_t)mtile * 128) << 14);
    const unsigned char* srcAl = (const unsigned char*)g_seq_lo + (((size_t)mtile * 128) << 14);
    const unsigned char* srcBh = (const unsigned char*)g_wih_hi + (((size_t)ntile * 128) << 14) + bhalf;
    const unsigned char* srcBl = (const unsigned char*)g_wih_lo + (((size_t)ntile * 128) << 14) + bhalf;

    auto issue_stage = [&](int st, int it) {
        uint32_t sb = dsm + st * STAGE_B;
        uint32_t fb = smem_u32(&s_full[st]);
        size_t off = (size_t)it << 14;
        MBARRIER_EXPECT_TX(fb, STAGE_B);
        BULK_G2S(sb,          srcAh + off, 16384, fb);
        BULK_G2S(sb + OFF_AL, srcAl + off, 16384, fb);
        BULK_G2S(sb + OFF_BH, srcBh + off,  8192, fb);
        BULK_G2S(sb + OFF_BL, srcBl + off,  8192, fb);
    };

    if (tid == 0) {
        issue_stage(0, 0);
        issue_stage(1, 1);
        issue_stage(2, 2);
    }

    const int rA  = warp_m * 32 + (lane & 7) + ((lane >> 3) & 1) * 8;
    const int aHf = lane >> 4;
    const int r7a = rA & 7;
    const int rB  = warp_n * 32 + (lane & 7) + ((lane >> 4) & 1) * 8;
    const int bHf = (lane >> 3) & 1;
    const int r7b = rB & 7;
    const uint32_t aoff0 = (uint32_t)rA * 128;
    const uint32_t aoff1 = aoff0 + 16 * 128;
    const uint32_t boff0 = (uint32_t)rB * 128;
    const uint32_t boff1 = boff0 + 16 * 128;

    float d[2][4][4];
#pragma unroll
    for (int i = 0; i < 2; i++)
#pragma unroll
        for (int j = 0; j < 4; j++)
#pragma unroll
            for (int q = 0; q < 4; q++) d[i][j][q] = 0.f;

    for (int it = 0; it < NIT; it++) {
        int s = it % NSTAGE;
        MBARRIER_WAIT_PARITY(smem_u32(&s_full[s]), (it / NSTAGE) & 1);

        uint32_t sA = dsm + s * STAGE_B;
        uint32_t sB = sA + OFF_BH;
#pragma unroll
        for (int ks = 0; ks < 4; ks++) {
            int kseg = ks * 2;
            uint32_t ah[2][4], al[2][4], bh[2][4], bl[2][4];
            {
                uint32_t asg = (uint32_t)(((kseg + aHf) ^ r7a) << 4);
                uint32_t ad0 = sA + aoff0 + asg;
                uint32_t ad1 = sA + aoff1 + asg;
                LDSM_X4(ah[0][0], ah[0][1], ah[0][2], ah[0][3], ad0);
                LDSM_X4(ah[1][0], ah[1][1], ah[1][2], ah[1][3], ad1);
                LDSM_X4(al[0][0], al[0][1], al[0][2], al[0][3], ad0 + OFF_AL);
                LDSM_X4(al[1][0], al[1][1], al[1][2], al[1][3], ad1 + OFF_AL);
            }
            {
                uint32_t bsg = (uint32_t)(((kseg + bHf) ^ r7b) << 4);
                uint32_t bd0 = sB + boff0 + bsg;
                uint32_t bd1 = sB + boff1 + bsg;
                LDSM_X4(bh[0][0], bh[0][1], bh[0][2], bh[0][3], bd0);
                LDSM_X4(bh[1][0], bh[1][1], bh[1][2], bh[1][3], bd1);
                LDSM_X4(bl[0][0], bl[0][1], bl[0][2], bl[0][3], bd0 + 8192);
                LDSM_X4(bl[1][0], bl[1][1], bl[1][2], bl[1][3], bd1 + 8192);
            }
#pragma unroll
            for (int mt = 0; mt < 2; mt++)
#pragma unroll
                for (int p = 0; p < 2; p++)
#pragma unroll
                    for (int hf = 0; hf < 2; hf++) {
                        float* dd = d[mt][p * 2 + hf];
                        mma16816(dd, ah[mt], &bh[p][hf * 2]);
                        mma16816(dd, ah[mt], &bl[p][hf * 2]);
                        mma16816(dd, al[mt], &bh[p][hf * 2]);
                    }
        }
        __syncthreads();
        if (tid == 0 && it + NSTAGE < NIT) issue_stage(s, it + NSTAGE);
    }

#pragma unroll
    for (int mt = 0; mt < 2; mt++) {
#pragma unroll
        for (int nt = 0; nt < 4; nt++) {
            int rowm = mblk + warp_m * 32 + mt * 16 + (lane >> 2);
            int coln = nblk + warp_n * 32 + nt * 8 + (lane & 3) * 2;
            float bi0 = b_ih[coln]     + b_hh[coln];
            float bi1 = b_ih[coln + 1] + b_hh[coln + 1];
            float* p0 = g_gates + (size_t)rowm * GN + coln;
            float* p1 = g_gates + (size_t)(rowm + 8) * GN + coln;
            float2 v0 = {d[mt][nt][0] + bi0, d[mt][nt][1] + bi1};
            float2 v1 = {d[mt][nt][2] + bi0, d[mt][nt][3] + bi1};
            *(float2*)p0 = v0;
            *(float2*)p1 = v1;
        }
    }
}

// ---------------------------------------------------------------------------
// Kernel 3: LSTM recurrence, coalesced packed-transposed W_hh.
// Thread g owns gate row g; lanes read consecutive float4 -> 4 lines/warp-LDG.
// ---------------------------------------------------------------------------
__global__ __launch_bounds__(1024) void lstm_kernel()
{
    __shared__ float hbuf[Hz];
    __shared__ float gbuf[G4];

    const int b = blockIdx.x;
    const int g = threadIdx.x;
    if (g < Hz) hbuf[g] = 0.f;
    float c = 0.f;

    const float* pre = g_gates + (size_t)b * Tz * G4;
    __syncthreads();

    for (int t = 0; t < Tz; t++) {
        float acc = pre[t * G4 + g];
#pragma unroll 16
        for (int k4 = 0; k4 < Hz / 4; k4++) {
            float4 w  = g_whhT[k4 * G4 + g];
            float4 h4 = *(const float4*)&hbuf[k4 * 4];
            acc = fmaf(w.x, h4.x, acc);
            acc = fmaf(w.y, h4.y, acc);
            acc = fmaf(w.z, h4.z, acc);
            acc = fmaf(w.w, h4.w, acc);
        }
        gbuf[g] = acc;
        __syncthreads();
        if (g < Hz) {
            float gi = 1.f / (1.f + __expf(-gbuf[g]));
            float gf = 1.f / (1.f + __expf(-gbuf[Hz + g]));
            float gg = tanhf(gbuf[2 * Hz + g]);
            float go = 1.f / (1.f + __expf(-gbuf[3 * Hz + g]));
            c = gf * c + gi * gg;
            hbuf[g] = go * tanhf(c);
        }
        __syncthreads();
    }
    if (g < Hz) g_hlast[b * Hz + g] = hbuf[g];
}

// ---------------------------------------------------------------------------
// Kernel 4: output linear
// ---------------------------------------------------------------------------
__global__ __launch_bounds__(256) void out_kernel(
    const float* __restrict__ Wo, const float* __restrict__ bo,
    float* __restrict__ out)
{
    const int b = blockIdx.x, n = threadIdx.x;
    const float4* h4 = (const float4*)(g_hlast + b * Hz);
    const float4* w4 = (const float4*)(Wo + n * Hz);
    float acc = bo[n];
#pragma unroll 8
    for (int k = 0; k < Hz / 4; k++) {
        float4 w = w4[k], h = h4[k];
        acc = fmaf(w.x, h.x, acc);
        acc = fmaf(w.y, h.y, acc);
        acc = fmaf(w.z, h.z, acc);
        acc = fmaf(w.w, h.w, acc);
    }
    out[b * Nz + n] = acc;
}

// ---------------------------------------------------------------------------
extern "C" void kernel_launch(void* const* d_in, const int* in_sizes, int n_in,
                              void* d_out, int out_size)
{
    const float* x     = (const float*)d_in[0];
    const float* adj   = (const float*)d_in[1];
    const float* W     = (const float*)d_in[2];
    const float* a_src = (const float*)d_in[3];
    const float* a_dst = (const float*)d_in[4];
    const float* gat_b = (const float*)d_in[5];
    const float* W_ih  = (const float*)d_in[6];
    const float* W_hh  = (const float*)d_in[7];
    const float* b_ih  = (const float*)d_in[8];
    const float* b_hh  = (const float*)d_in[9];
    const float* Wo    = (const float*)d_in[10];
    const float* bo    = (const float*)d_in[11];
    float* out = (float*)d_out;

    cudaFuncSetAttribute(tc_gemm_kernel,
                         cudaFuncAttributeMaxDynamicSharedMemorySize, SMEM_DYN);

    // Launch order puts tc_gemm at list position 3 -> the ncu-profiled slot.
    conv_wih_kernel<<<(int)(((size_t)GN * GK / 8) / 256), 256>>>(W_ih);   // 0
    gat_kernel<<<GM, 256>>>(x, adj, W, a_src, a_dst, gat_b);              // 1
    conv_whh_kernel<<<256, 256>>>(W_hh);                                  // 2

    dim3 gg(GN / BN, GM / BM);   // 16 x 8 = 128 CTAs
    tc_gemm_kernel<<<gg, 256, SMEM_DYN>>>(b_ih, b_hh);                    // 3 (profiled)

    lstm_kernel<<<Bz, 1024>>>();                                          // 4
    out_kernel<<<Bz, 256>>>(Wo, bo, out);                                 // 5
}

// round 7
// speedup vs baseline: 3.1017x; 1.4024x over previous
#include <cuda_runtime.h>
#include <cuda_bf16.h>
#include <math.h>
#include <stdint.h>

// Problem dims
#define Bz   32
#define Tz   32
#define Nz   256
#define FIN  32
#define FOUT 32
#define Hz   256
#define INz  8192
#define G4   1024
#define GM   1024   // Bz*Tz rows of seq
#define GK   8192
#define GN   1024

// GEMM tiling
#define BM 128
#define BN 64
#define BK 64
#define NIT (GK / BK)          // 128
#define NSTAGE 3
#define OFF_AL 16384
#define OFF_BH 32768
#define OFF_BL 40960
#define STAGE_B 49152          // Ah16K + Al16K + Bh8K + Bl8K
#define SMEM_DYN (NSTAGE * STAGE_B)   // 144 KB

// ---------------------------------------------------------------------------
// Scratch. seq/wih in ldmatrix-swizzled tiled layout:
// offset = ((rowtile*128 + kchunk) << 14) + row*128 + ((seg^(row&7))<<4) + (k&7)*2
// ---------------------------------------------------------------------------
__device__ __align__(128) __nv_bfloat16 g_seq_hi[(size_t)GM * GK];
__device__ __align__(128) __nv_bfloat16 g_seq_lo[(size_t)GM * GK];
__device__ __align__(128) __nv_bfloat16 g_wih_hi[(size_t)GN * GK];
__device__ __align__(128) __nv_bfloat16 g_wih_lo[(size_t)GN * GK];
__device__ float g_gates[(size_t)GM * G4];
__device__ float4 g_whhT[(Hz / 4) * G4];    // packed transpose: [k/4][g]
__device__ float g_hlast[Bz * Hz];

// ---------------------------------------------------------------------------
// PTX helpers (baseline features only — nothing 'a'-suffix)
// ---------------------------------------------------------------------------
__device__ __forceinline__ uint32_t smem_u32(const void* p) {
    return (uint32_t)__cvta_generic_to_shared(p);
}

#define MBARRIER_INIT(addr, cnt) \
    asm volatile("mbarrier.init.shared.b64 [%0], %1;" :: "r"(addr), "r"(cnt) : "memory")
#define MBARRIER_EXPECT_TX(addr, bytes) \
    asm volatile("mbarrier.arrive.expect_tx.shared.b64 _, [%0], %1;" :: "r"(addr), "r"(bytes) : "memory")
#define MBARRIER_WAIT_PARITY(addr, par) do {                                        \
    uint32_t _mbar = (addr); uint32_t _p = (par); uint32_t _done;                   \
    asm volatile("{\n\t.reg .pred p;\n\t"                                           \
        "mbarrier.try_wait.parity.acquire.cta.shared::cta.b64 p, [%1], %2;\n\t"     \
        "selp.b32 %0, 1, 0, p;\n\t}"                                                \
        : "=r"(_done) : "r"(_mbar), "r"(_p) : "memory");                            \
    if (!_done) {                                                                   \
        asm volatile("{\n\t.reg .pred P1;\n\t"                                      \
            "WAIT_LOOP_%=:\n\t"                                                     \
            "mbarrier.try_wait.parity.acquire.cta.shared::cta.b64 P1, [%0], %1, 0x989680;\n\t" \
            "@P1 bra.uni WAIT_DONE_%=;\n\t"                                         \
            "bra.uni WAIT_LOOP_%=;\n\t"                                             \
            "WAIT_DONE_%=:\n\t}"                                                    \
            :: "r"(_mbar), "r"(_p) : "memory");                                     \
    } } while (0)

#define BULK_G2S(dst, src, bytes, mbar) \
    asm volatile("cp.async.bulk.shared::cluster.global.mbarrier::complete_tx::bytes [%0], [%1], %2, [%3];" \
        :: "r"(dst), "l"(src), "r"(bytes), "r"(mbar) : "memory")

#define FENCE_ASYNC() asm volatile("fence.proxy.async.shared::cta;" ::: "memory")

#define LDSM_X4(r0, r1, r2, r3, addr) \
    asm volatile("ldmatrix.sync.aligned.m8n8.x4.shared.b16 {%0,%1,%2,%3}, [%4];" \
        : "=r"(r0), "=r"(r1), "=r"(r2), "=r"(r3) : "r"(addr))

__device__ __forceinline__ void mma16816(float* d, const uint32_t* a, const uint32_t* b) {
    asm volatile(
        "mma.sync.aligned.m16n8k16.row.col.f32.bf16.bf16.f32 "
        "{%0,%1,%2,%3}, {%4,%5,%6,%7}, {%8,%9}, {%0,%1,%2,%3};"
        : "+f"(d[0]), "+f"(d[1]), "+f"(d[2]), "+f"(d[3])
        : "r"(a[0]), "r"(a[1]), "r"(a[2]), "r"(a[3]), "r"(b[0]), "r"(b[1]));
}

// Packed f32x2 FMA (sm_100+ base PTX)
#define FMA_F32X2(acc, a, b) \
    asm("fma.rn.f32x2 %0, %1, %2, %0;" : "+l"(acc) : "l"(a), "l"(b))
#define PACK_F32X2(out, lo, hi) \
    asm("mov.b64 %0, {%1, %2};" : "=l"(out) : "f"(lo), "f"(hi))
#define UNPACK_F32X2(lo, hi, in) \
    asm("mov.b64 {%0, %1}, %2;" : "=f"(lo), "=f"(hi) : "l"(in))

__device__ __forceinline__ uint32_t pack_bf16x2(float v0, float v1) {
    unsigned short a = __bfloat16_as_ushort(__float2bfloat16(v0));
    unsigned short b = __bfloat16_as_ushort(__float2bfloat16(v1));
    return ((uint32_t)b << 16) | a;
}
__device__ __forceinline__ void split_bf16(float v, float& hi, float& lo) {
    __nv_bfloat16 h = __float2bfloat16(v);
    hi = __bfloat162float(h);
    lo = v - hi;
}

// ---------------------------------------------------------------------------
// Kernel 1: GAT per (b,t). Batched adj loads (MLP=16) + packed f32x2 FMA sweep.
// ---------------------------------------------------------------------------
__global__ __launch_bounds__(256) void gat_kernel(
    const float* __restrict__ x, const float* __restrict__ adj,
    const float* __restrict__ W, const float* __restrict__ a_src,
    const float* __restrict__ a_dst, const float* __restrict__ gat_b)
{
    __shared__ float sh[Nz][36];    // 144B rows -> 16B aligned
    __shared__ float ssrc[Nz];
    __shared__ float sW[FIN][FOUT];
    __shared__ float sas[FOUT], sad[FOUT], sbias[FOUT];

    const int bt  = blockIdx.x;
    const int tid = threadIdx.x;
    const float* xb   = x   + (size_t)bt * Nz * FIN;
    const float* adjb = adj + (size_t)bt * Nz * Nz;

    for (int i = tid; i < FIN * FOUT; i += 256) sW[i / FOUT][i % FOUT] = W[i];
    if (tid < FOUT) { sas[tid] = a_src[tid]; sad[tid] = a_dst[tid]; sbias[tid] = gat_b[tid]; }
    __syncthreads();

    float xv[FIN];
#pragma unroll
    for (int k = 0; k < FIN; k++) xv[k] = xb[tid * FIN + k];
    float vsrc = 0.f, vdst = 0.f;
#pragma unroll
    for (int o = 0; o < FOUT; o++) {
        float acc = 0.f;
#pragma unroll
        for (int k = 0; k < FIN; k++) acc = fmaf(xv[k], sW[k][o], acc);
        sh[tid][o] = acc;
        vsrc = fmaf(acc, sas[o], vsrc);
        vdst = fmaf(acc, sad[o], vdst);
    }
    ssrc[tid] = vsrc;
    __syncthreads();

    float l0 = 0.f, l1 = 0.f;
    unsigned long long acc2[16];
#pragma unroll
    for (int q = 0; q < 16; q++) PACK_F32X2(acc2[q], 0.f, 0.f);

    for (int c = 0; c < Nz; c += 16) {
        // phase A: 16 batched adj loads + branch-free p
        float p[16];
#pragma unroll
        for (int jj = 0; jj < 16; jj++) {
            float av = adjb[(size_t)(c + jj) * Nz + tid];
            float e = vdst + ssrc[c + jj];
            e = (e > 0.f) ? e : 0.2f * e;
            float pe = __expf(e);
            bool edge = (av != 0.f) | ((c + jj) == tid);
            p[jj] = edge ? pe : 0.f;
            if (jj & 1) l1 += p[jj]; else l0 += p[jj];
        }
        // phase B: packed f32x2 weighted accumulation from smem
#pragma unroll
        for (int jj = 0; jj < 16; jj++) {
            unsigned long long pp;
            PACK_F32X2(pp, p[jj], p[jj]);
            const ulonglong2* hj = (const ulonglong2*)&sh[c + jj][0];
#pragma unroll
            for (int q = 0; q < 8; q++) {
                ulonglong2 hv = hj[q];
                FMA_F32X2(acc2[2*q],     pp, hv.x);
                FMA_F32X2(acc2[2*q + 1], pp, hv.y);
            }
        }
    }

    float inv = 1.f / (l0 + l1);   // > 0 (self loop)
    float vh[FOUT], vl[FOUT];
#pragma unroll
    for (int q = 0; q < 16; q++) {
        float a0, a1;
        UNPACK_F32X2(a0, a1, acc2[q]);
        float v0 = fmaf(a0, inv, sbias[2*q]);
        float v1 = fmaf(a1, inv, sbias[2*q + 1]);
        split_bf16(v0, vh[2*q],     vl[2*q]);
        split_bf16(v1, vh[2*q + 1], vl[2*q + 1]);
    }

    const int mtile = bt >> 7, mrow = bt & 127;
    const int chunk = tid >> 1;
    const int seg0  = (tid & 1) * 4;
    unsigned char* baseh = (unsigned char*)g_seq_hi + (((size_t)(mtile * 128 + chunk)) << 14) + mrow * 128;
    unsigned char* basel = (unsigned char*)g_seq_lo + (((size_t)(mtile * 128 + chunk)) << 14) + mrow * 128;
#pragma unroll
    for (int g = 0; g < 4; g++) {
        uint32_t sw = (uint32_t)(((seg0 + g) ^ (mrow & 7)) << 4);
        uint4 uh, ul;
        uh.x = pack_bf16x2(vh[g*8+0], vh[g*8+1]);
        uh.y = pack_bf16x2(vh[g*8+2], vh[g*8+3]);
        uh.z = pack_bf16x2(vh[g*8+4], vh[g*8+5]);
        uh.w = pack_bf16x2(vh[g*8+6], vh[g*8+7]);
        ul.x = pack_bf16x2(vl[g*8+0], vl[g*8+1]);
        ul.y = pack_bf16x2(vl[g*8+2], vl[g*8+3]);
        ul.z = pack_bf16x2(vl[g*8+4], vl[g*8+5]);
        ul.w = pack_bf16x2(vl[g*8+6], vl[g*8+7]);
        *(uint4*)(baseh + sw) = uh;
        *(uint4*)(basel + sw) = ul;
    }
}

// ---------------------------------------------------------------------------
// Kernel 1b: W_ih fp32 -> swizzled tiled bf16 hi/lo (half of rows per launch)
// ---------------------------------------------------------------------------
__global__ __launch_bounds__(256) void conv_wih_kernel(const float* __restrict__ W_ih, int n0)
{
    size_t t = (size_t)blockIdx.x * 256 + threadIdx.x;
    int n = n0 + (int)(t >> 10);
    int s = (int)(t & 1023);
    int k0 = s * 8;
    const float* src = W_ih + (size_t)n * GK + k0;
    float4 v0 = *(const float4*)(src);
    float4 v1 = *(const float4*)(src + 4);
    float f[8] = {v0.x, v0.y, v0.z, v0.w, v1.x, v1.y, v1.z, v1.w};
    float fh[8], fl[8];
#pragma unroll
    for (int i = 0; i < 8; i++) split_bf16(f[i], fh[i], fl[i]);

    int ntile = n >> 7, nrow = n & 127, chunk = s >> 3, seg = s & 7;
    size_t off = (((size_t)(ntile * 128 + chunk)) << 14) + nrow * 128
               + (uint32_t)((seg ^ (nrow & 7)) << 4);
    uint4 uh, ul;
    uh.x = pack_bf16x2(fh[0], fh[1]); uh.y = pack_bf16x2(fh[2], fh[3]);
    uh.z = pack_bf16x2(fh[4], fh[5]); uh.w = pack_bf16x2(fh[6], fh[7]);
    ul.x = pack_bf16x2(fl[0], fl[1]); ul.y = pack_bf16x2(fl[2], fl[3]);
    ul.z = pack_bf16x2(fl[4], fl[5]); ul.w = pack_bf16x2(fl[6], fl[7]);
    *(uint4*)((unsigned char*)g_wih_hi + off) = uh;
    *(uint4*)((unsigned char*)g_wih_lo + off) = ul;
}

// ---------------------------------------------------------------------------
// Kernel 1c: W_hh [G4][Hz] -> packed transpose g_whhT[k/4][g]
// ---------------------------------------------------------------------------
__global__ __launch_bounds__(256) void conv_whh_kernel(const float* __restrict__ W_hh)
{
    int t = blockIdx.x * 256 + threadIdx.x;
    int g  = t & 1023;
    int k4 = t >> 10;
    float4 v = *(const float4*)(W_hh + (size_t)g * Hz + k4 * 4);
    g_whhT[k4 * G4 + g] = v;
}

// ---------------------------------------------------------------------------
// Kernel 2: split-bf16 mma.sync GEMM fed by cp.async.bulk + mbarrier.
// ---------------------------------------------------------------------------
__global__ __launch_bounds__(256) void tc_gemm_kernel(
    const float* __restrict__ b_ih, const float* __restrict__ b_hh)
{
    extern __shared__ __align__(128) unsigned char dsmem[];
    __shared__ __align__(8) unsigned long long s_full[NSTAGE];
    const uint32_t dsm = smem_u32(dsmem);

    const int tid  = threadIdx.x;
    const int lane = tid & 31;
    const int wid  = tid >> 5;
    const int warp_m = wid >> 1;
    const int warp_n = wid & 1;
    const int mblk = blockIdx.y * BM;
    const int nblk = blockIdx.x * BN;
    const int mtile = blockIdx.y;
    const int ntile = blockIdx.x >> 1;
    const size_t bhalf = (size_t)(blockIdx.x & 1) * 8192;

    if (tid == 0) {
        for (int p = 0; p < NSTAGE; p++) MBARRIER_INIT(smem_u32(&s_full[p]), 1);
        FENCE_ASYNC();
    }
    __syncthreads();

    const unsigned char* srcAh = (const unsigned char*)g_seq_hi + (((size_t)mtile * 128) << 14);
    const unsigned char* srcAl = (const unsigned char*)g_seq_lo + (((size_t)mtile * 128) << 14);
    const unsigned char* srcBh = (const unsigned char*)g_wih_hi + (((size_t)ntile * 128) << 14) + bhalf;
    const unsigned char* srcBl = (const unsigned char*)g_wih_lo + (((size_t)ntile * 128) << 14) + bhalf;

    auto issue_stage = [&](int st, int it) {
        uint32_t sb = dsm + st * STAGE_B;
        uint32_t fb = smem_u32(&s_full[st]);
        size_t off = (size_t)it << 14;
        MBARRIER_EXPECT_TX(fb, STAGE_B);
        BULK_G2S(sb,          srcAh + off, 16384, fb);
        BULK_G2S(sb + OFF_AL, srcAl + off, 16384, fb);
        BULK_G2S(sb + OFF_BH, srcBh + off,  8192, fb);
        BULK_G2S(sb + OFF_BL, srcBl + off,  8192, fb);
    };

    if (tid == 0) {
        issue_stage(0, 0);
        issue_stage(1, 1);
        issue_stage(2, 2);
    }

    const int rA  = warp_m * 32 + (lane & 7) + ((lane >> 3) & 1) * 8;
    const int aHf = lane >> 4;
    const int r7a = rA & 7;
    const int rB  = warp_n * 32 + (lane & 7) + ((lane >> 4) & 1) * 8;
    const int bHf = (lane >> 3) & 1;
    const int r7b = rB & 7;
    const uint32_t aoff0 = (uint32_t)rA * 128;
    const uint32_t aoff1 = aoff0 + 16 * 128;
    const uint32_t boff0 = (uint32_t)rB * 128;
    const uint32_t boff1 = boff0 + 16 * 128;

    float d[2][4][4];
#pragma unroll
    for (int i = 0; i < 2; i++)
#pragma unroll
        for (int j = 0; j < 4; j++)
#pragma unroll
            for (int q = 0; q < 4; q++) d[i][j][q] = 0.f;

    for (int it = 0; it < NIT; it++) {
        int s = it % NSTAGE;
        MBARRIER_WAIT_PARITY(smem_u32(&s_full[s]), (it / NSTAGE) & 1);

        uint32_t sA = dsm + s * STAGE_B;
        uint32_t sB = sA + OFF_BH;
#pragma unroll
        for (int ks = 0; ks < 4; ks++) {
            int kseg = ks * 2;
            uint32_t ah[2][4], al[2][4], bh[2][4], bl[2][4];
            {
                uint32_t asg = (uint32_t)(((kseg + aHf) ^ r7a) << 4);
                uint32_t ad0 = sA + aoff0 + asg;
                uint32_t ad1 = sA + aoff1 + asg;
                LDSM_X4(ah[0][0], ah[0][1], ah[0][2], ah[0][3], ad0);
                LDSM_X4(ah[1][0], ah[1][1], ah[1][2], ah[1][3], ad1);
                LDSM_X4(al[0][0], al[0][1], al[0][2], al[0][3], ad0 + OFF_AL);
                LDSM_X4(al[1][0], al[1][1], al[1][2], al[1][3], ad1 + OFF_AL);
            }
            {
                uint32_t bsg = (uint32_t)(((kseg + bHf) ^ r7b) << 4);
                uint32_t bd0 = sB + boff0 + bsg;
                uint32_t bd1 = sB + boff1 + bsg;
                LDSM_X4(bh[0][0], bh[0][1], bh[0][2], bh[0][3], bd0);
                LDSM_X4(bh[1][0], bh[1][1], bh[1][2], bh[1][3], bd1);
                LDSM_X4(bl[0][0], bl[0][1], bl[0][2], bl[0][3], bd0 + 8192);
                LDSM_X4(bl[1][0], bl[1][1], bl[1][2], bl[1][3], bd1 + 8192);
            }
#pragma unroll
            for (int mt = 0; mt < 2; mt++)
#pragma unroll
                for (int p = 0; p < 2; p++)
#pragma unroll
                    for (int hf = 0; hf < 2; hf++) {
                        float* dd = d[mt][p * 2 + hf];
                        mma16816(dd, ah[mt], &bh[p][hf * 2]);
                        mma16816(dd, ah[mt], &bl[p][hf * 2]);
                        mma16816(dd, al[mt], &bh[p][hf * 2]);
                    }
        }
        __syncthreads();
        if (tid == 0 && it + NSTAGE < NIT) issue_stage(s, it + NSTAGE);
    }

#pragma unroll
    for (int mt = 0; mt < 2; mt++) {
#pragma unroll
        for (int nt = 0; nt < 4; nt++) {
            int rowm = mblk + warp_m * 32 + mt * 16 + (lane >> 2);
            int coln = nblk + warp_n * 32 + nt * 8 + (lane & 3) * 2;
            float bi0 = b_ih[coln]     + b_hh[coln];
            float bi1 = b_ih[coln + 1] + b_hh[coln + 1];
            float* p0 = g_gates + (size_t)rowm * GN + coln;
            float* p1 = g_gates + (size_t)(rowm + 8) * GN + coln;
            float2 v0 = {d[mt][nt][0] + bi0, d[mt][nt][1] + bi1};
            float2 v1 = {d[mt][nt][2] + bi0, d[mt][nt][3] + bi1};
            *(float2*)p0 = v0;
            *(float2*)p1 = v1;
        }
    }
}

// ---------------------------------------------------------------------------
// Kernel 3: LSTM recurrence, coalesced packed-transposed W_hh.
// ---------------------------------------------------------------------------
__global__ __launch_bounds__(1024) void lstm_kernel()
{
    __shared__ float hbuf[Hz];
    __shared__ float gbuf[G4];

    const int b = blockIdx.x;
    const int g = threadIdx.x;
    if (g < Hz) hbuf[g] = 0.f;
    float c = 0.f;

    const float* pre = g_gates + (size_t)b * Tz * G4;
    __syncthreads();

    for (int t = 0; t < Tz; t++) {
        float acc = pre[t * G4 + g];
#pragma unroll 16
        for (int k4 = 0; k4 < Hz / 4; k4++) {
            float4 w  = g_whhT[k4 * G4 + g];
            float4 h4 = *(const float4*)&hbuf[k4 * 4];
            acc = fmaf(w.x, h4.x, acc);
            acc = fmaf(w.y, h4.y, acc);
            acc = fmaf(w.z, h4.z, acc);
            acc = fmaf(w.w, h4.w, acc);
        }
        gbuf[g] = acc;
        __syncthreads();
        if (g < Hz) {
            float gi = 1.f / (1.f + __expf(-gbuf[g]));
            float gf = 1.f / (1.f + __expf(-gbuf[Hz + g]));
            float gg = tanhf(gbuf[2 * Hz + g]);
            float go = 1.f / (1.f + __expf(-gbuf[3 * Hz + g]));
            c = gf * c + gi * gg;
            hbuf[g] = go * tanhf(c);
        }
        __syncthreads();
    }
    if (g < Hz) g_hlast[b * Hz + g] = hbuf[g];
}

// ---------------------------------------------------------------------------
// Kernel 4: output linear
// ---------------------------------------------------------------------------
__global__ __launch_bounds__(256) void out_kernel(
    const float* __restrict__ Wo, const float* __restrict__ bo,
    float* __restrict__ out)
{
    const int b = blockIdx.x, n = threadIdx.x;
    const float4* h4 = (const float4*)(g_hlast + b * Hz);
    const float4* w4 = (const float4*)(Wo + n * Hz);
    float acc = bo[n];
#pragma unroll 8
    for (int k = 0; k < Hz / 4; k++) {
        float4 w = w4[k], h = h4[k];
        acc = fmaf(w.x, h.x, acc);
        acc = fmaf(w.y, h.y, acc);
        acc = fmaf(w.z, h.z, acc);
        acc = fmaf(w.w, h.w, acc);
    }
    out[b * Nz + n] = acc;
}

// ---------------------------------------------------------------------------
extern "C" void kernel_launch(void* const* d_in, const int* in_sizes, int n_in,
                              void* d_out, int out_size)
{
    const float* x     = (const float*)d_in[0];
    const float* adj   = (const float*)d_in[1];
    const float* W     = (const float*)d_in[2];
    const float* a_src = (const float*)d_in[3];
    const float* a_dst = (const float*)d_in[4];
    const float* gat_b = (const float*)d_in[5];
    const float* W_ih  = (const float*)d_in[6];
    const float* W_hh  = (const float*)d_in[7];
    const float* b_ih  = (const float*)d_in[8];
    const float* b_hh  = (const float*)d_in[9];
    const float* Wo    = (const float*)d_in[10];
    const float* bo    = (const float*)d_in[11];
    float* out = (float*)d_out;

    cudaFuncSetAttribute(tc_gemm_kernel,
                         cudaFuncAttributeMaxDynamicSharedMemorySize, SMEM_DYN);

    // 4th launch (index 3) lands in the ncu profiled slot -> gat this round.
    conv_wih_kernel<<<2048, 256>>>(W_ih, 0);                              // 0
    conv_wih_kernel<<<2048, 256>>>(W_ih, 512);                            // 1
    conv_whh_kernel<<<256, 256>>>(W_hh);                                  // 2
    gat_kernel<<<GM, 256>>>(x, adj, W, a_src, a_dst, gat_b);              // 3 (profiled)

    dim3 gg(GN / BN, GM / BM);   // 16 x 8 = 128 CTAs
    tc_gemm_kernel<<<gg, 256, SMEM_DYN>>>(b_ih, b_hh);                    // 4

    lstm_kernel<<<Bz, 1024>>>();                                          // 5
    out_kernel<<<Bz, 256>>>(Wo, bo, out);                                 // 6
}

// round 8
// speedup vs baseline: 3.6452x; 1.1752x over previous
#include <cuda_runtime.h>
#include <cuda_bf16.h>
#include <math.h>
#include <stdint.h>

// Problem dims
#define Bz   32
#define Tz   32
#define Nz   256
#define FIN  32
#define FOUT 32
#define Hz   256
#define INz  8192
#define G4   1024
#define GM   1024   // Bz*Tz rows of seq
#define GK   8192
#define GN   1024

// GEMM tiling
#define BM 128
#define BN 64
#define BK 64
#define NIT (GK / BK)          // 128
#define NSTAGE 3
#define OFF_AL 16384
#define OFF_BH 32768
#define OFF_BL 40960
#define STAGE_B 49152
#define SMEM_DYN (NSTAGE * STAGE_B)   // 144 KB

// GAT smem layout (dynamic)
#define GAT_SH_HI   0        // h hi bf16 [256][32] rows 64B
#define GAT_SH_LO   16384
#define GAT_AL_HI   32768    // alpha hi bf16 [2 bufs][256][16] rows 32B
#define GAT_AL_LO   49152
#define GAT_SSRC    65536
#define GAT_SL      66560
#define GAT_SW      67584    // W [32][32] f32
#define GAT_SAS     71680
#define GAT_SAD     71808
#define GAT_SBIAS   71936
#define SMEM_GAT    72064

// ---------------------------------------------------------------------------
// Scratch. seq/wih in ldmatrix-swizzled tiled layout:
// offset = ((rowtile*128 + kchunk) << 14) + row*128 + ((seg^(row&7))<<4) + (k&7)*2
// ---------------------------------------------------------------------------
__device__ __align__(128) __nv_bfloat16 g_seq_hi[(size_t)GM * GK];
__device__ __align__(128) __nv_bfloat16 g_seq_lo[(size_t)GM * GK];
__device__ __align__(128) __nv_bfloat16 g_wih_hi[(size_t)GN * GK];
__device__ __align__(128) __nv_bfloat16 g_wih_lo[(size_t)GN * GK];
__device__ float g_gates[(size_t)GM * G4];
__device__ float4 g_whhT[(Hz / 4) * G4];
__device__ float g_hlast[Bz * Hz];

// ---------------------------------------------------------------------------
// PTX helpers (baseline features only)
// ---------------------------------------------------------------------------
__device__ __forceinline__ uint32_t smem_u32(const void* p) {
    return (uint32_t)__cvta_generic_to_shared(p);
}

#define MBARRIER_INIT(addr, cnt) \
    asm volatile("mbarrier.init.shared.b64 [%0], %1;" :: "r"(addr), "r"(cnt) : "memory")
#define MBARRIER_EXPECT_TX(addr, bytes) \
    asm volatile("mbarrier.arrive.expect_tx.shared.b64 _, [%0], %1;" :: "r"(addr), "r"(bytes) : "memory")
#define MBARRIER_WAIT_PARITY(addr, par) do {                                        \
    uint32_t _mbar = (addr); uint32_t _p = (par); uint32_t _done;                   \
    asm volatile("{\n\t.reg .pred p;\n\t"                                           \
        "mbarrier.try_wait.parity.acquire.cta.shared::cta.b64 p, [%1], %2;\n\t"     \
        "selp.b32 %0, 1, 0, p;\n\t}"                                                \
        : "=r"(_done) : "r"(_mbar), "r"(_p) : "memory");                            \
    if (!_done) {                                                                   \
        asm volatile("{\n\t.reg .pred P1;\n\t"                                      \
            "WAIT_LOOP_%=:\n\t"                                                     \
            "mbarrier.try_wait.parity.acquire.cta.shared::cta.b64 P1, [%0], %1, 0x989680;\n\t" \
            "@P1 bra.uni WAIT_DONE_%=;\n\t"                                         \
            "bra.uni WAIT_LOOP_%=;\n\t"                                             \
            "WAIT_DONE_%=:\n\t}"                                                    \
            :: "r"(_mbar), "r"(_p) : "memory");                                     \
    } } while (0)

#define BULK_G2S(dst, src, bytes, mbar) \
    asm volatile("cp.async.bulk.shared::cluster.global.mbarrier::complete_tx::bytes [%0], [%1], %2, [%3];" \
        :: "r"(dst), "l"(src), "r"(bytes), "r"(mbar) : "memory")

#define FENCE_ASYNC() asm volatile("fence.proxy.async.shared::cta;" ::: "memory")

#define LDSM_X4(r0, r1, r2, r3, addr) \
    asm volatile("ldmatrix.sync.aligned.m8n8.x4.shared.b16 {%0,%1,%2,%3}, [%4];" \
        : "=r"(r0), "=r"(r1), "=r"(r2), "=r"(r3) : "r"(addr))
#define LDSM_X4T(r0, r1, r2, r3, addr) \
    asm volatile("ldmatrix.sync.aligned.m8n8.x4.trans.shared.b16 {%0,%1,%2,%3}, [%4];" \
        : "=r"(r0), "=r"(r1), "=r"(r2), "=r"(r3) : "r"(addr))

__device__ __forceinline__ void mma16816(float* d, const uint32_t* a, const uint32_t* b) {
    asm volatile(
        "mma.sync.aligned.m16n8k16.row.col.f32.bf16.bf16.f32 "
        "{%0,%1,%2,%3}, {%4,%5,%6,%7}, {%8,%9}, {%0,%1,%2,%3};"
        : "+f"(d[0]), "+f"(d[1]), "+f"(d[2]), "+f"(d[3])
        : "r"(a[0]), "r"(a[1]), "r"(a[2]), "r"(a[3]), "r"(b[0]), "r"(b[1]));
}

__device__ __forceinline__ uint32_t pack_bf16x2(float v0, float v1) {
    unsigned short a = __bfloat16_as_ushort(__float2bfloat16(v0));
    unsigned short b = __bfloat16_as_ushort(__float2bfloat16(v1));
    return ((uint32_t)b << 16) | a;
}
__device__ __forceinline__ void split_bf16(float v, float& hi, float& lo) {
    __nv_bfloat16 h = __float2bfloat16(v);
    hi = __bfloat162float(h);
    lo = v - hi;
}

// ---------------------------------------------------------------------------
// Kernel 1: GAT per (b,t). alpha@h on tensor cores (split-bf16, 3 passes).
// ---------------------------------------------------------------------------
__global__ __launch_bounds__(256) void gat_kernel(
    const float* __restrict__ x, const float* __restrict__ adj,
    const float* __restrict__ W, const float* __restrict__ a_src,
    const float* __restrict__ a_dst, const float* __restrict__ gat_b)
{
    extern __shared__ __align__(128) unsigned char gsm[];
    const uint32_t smb = smem_u32(gsm);
    float* ssrc_f  = (float*)(gsm + GAT_SSRC);
    float* sl_f    = (float*)(gsm + GAT_SL);
    float* sW_f    = (float*)(gsm + GAT_SW);
    float* sas_f   = (float*)(gsm + GAT_SAS);
    float* sad_f   = (float*)(gsm + GAT_SAD);
    float* sbias_f = (float*)(gsm + GAT_SBIAS);

    const int bt  = blockIdx.x;
    const int tid = threadIdx.x;
    const int lane = tid & 31;
    const int wid  = tid >> 5;
    const float* xb   = x   + (size_t)bt * Nz * FIN;
    const float* adjb = adj + (size_t)bt * Nz * Nz;

    for (int i = tid; i < FIN * FOUT; i += 256) sW_f[i] = W[i];
    if (tid < FOUT) { sas_f[tid] = a_src[tid]; sad_f[tid] = a_dst[tid]; sbias_f[tid] = gat_b[tid]; }
    __syncthreads();

    // ---- phase 1: h row for node tid; write bf16 hi/lo rows to smem ----
    float xv[FIN];
#pragma unroll
    for (int k = 0; k < FIN; k++) xv[k] = xb[tid * FIN + k];
    float hv[FOUT];
    float vsrc = 0.f, vdst = 0.f;
#pragma unroll
    for (int o = 0; o < FOUT; o++) {
        float acc = 0.f;
#pragma unroll
        for (int k = 0; k < FIN; k++) acc = fmaf(xv[k], sW_f[k * FOUT + o], acc);
        hv[o] = acc;
        vsrc = fmaf(acc, sas_f[o], vsrc);
        vdst = fmaf(acc, sad_f[o], vdst);
    }
    ssrc_f[tid] = vsrc;
#pragma unroll
    for (int g = 0; g < 4; g++) {
        float h8h[8], h8l[8];
#pragma unroll
        for (int e = 0; e < 8; e++) split_bf16(hv[g*8 + e], h8h[e], h8l[e]);
        uint4 uh = { pack_bf16x2(h8h[0],h8h[1]), pack_bf16x2(h8h[2],h8h[3]),
                     pack_bf16x2(h8h[4],h8h[5]), pack_bf16x2(h8h[6],h8h[7]) };
        uint4 ul = { pack_bf16x2(h8l[0],h8l[1]), pack_bf16x2(h8l[2],h8l[3]),
                     pack_bf16x2(h8l[4],h8l[5]), pack_bf16x2(h8l[6],h8l[7]) };
        *(uint4*)(gsm + GAT_SH_HI + tid * 64 + g * 16) = uh;
        *(uint4*)(gsm + GAT_SH_LO + tid * 64 + g * 16) = ul;
    }
    __syncthreads();

    // ---- phase 2: chunks of 16 sources; alpha -> smem; MMA accumulate ----
    float d[2][4][4];
#pragma unroll
    for (int i = 0; i < 2; i++)
#pragma unroll
        for (int j = 0; j < 4; j++)
#pragma unroll
            for (int q = 0; q < 4; q++) d[i][j][q] = 0.f;
    float l = 0.f;

    const int i0 = wid * 32;
    // ldmatrix lane addressing (same decomposition for A and trans-B)
    const uint32_t lrow = (lane & 7) + ((lane >> 3) & 1) * 8;
    const uint32_t lhalf = (lane >> 4) & 1;
    const uint32_t aAddrBase = smb + GAT_AL_HI + (i0 + lrow) * 32 + lhalf * 16;
    const uint32_t bAddrBase = smb + GAT_SH_HI + lrow * 64 + lhalf * 16;

    for (int c = 0; c < 16; c++) {
        const int buf = c & 1;
        // --- alpha for target i=tid, sources j = c*16 .. c*16+15 ---
        float av[16];
#pragma unroll
        for (int jj = 0; jj < 16; jj++)
            av[jj] = adjb[(size_t)(c * 16 + jj) * Nz + tid];
        uint32_t phi[8], plo[8];
#pragma unroll
        for (int q = 0; q < 8; q++) {
            float p2[2];
#pragma unroll
            for (int u = 0; u < 2; u++) {
                int jj = q * 2 + u;
                int j  = c * 16 + jj;
                float e = vdst + ssrc_f[j];
                e = (e > 0.f) ? e : 0.2f * e;
                float pe = __expf(e);
                bool edge = (av[jj] != 0.f) | (j == tid);
                p2[u] = edge ? pe : 0.f;
                l += p2[u];
            }
            float h0, l0, h1, l1;
            split_bf16(p2[0], h0, l0);
            split_bf16(p2[1], h1, l1);
            phi[q] = pack_bf16x2(h0, h1);
            plo[q] = pack_bf16x2(l0, l1);
        }
        {
            unsigned char* arow = gsm + buf * 8192 + tid * 32;
            *(uint4*)(arow + GAT_AL_HI)      = *(uint4*)&phi[0];
            *(uint4*)(arow + GAT_AL_HI + 16) = *(uint4*)&phi[4];
            *(uint4*)(arow + GAT_AL_LO)      = *(uint4*)&plo[0];
            *(uint4*)(arow + GAT_AL_LO + 16) = *(uint4*)&plo[4];
        }
        __syncthreads();

        // --- MMA: out_stripe[i0..i0+31][0..31] += alpha_chunk @ h_chunk ---
        uint32_t ah[2][4], al[2][4], bh[2][4], bl[2][4];
        uint32_t aA = aAddrBase + buf * 8192;
        LDSM_X4(ah[0][0], ah[0][1], ah[0][2], ah[0][3], aA);
        LDSM_X4(ah[1][0], ah[1][1], ah[1][2], ah[1][3], aA + 16 * 32);
        LDSM_X4(al[0][0], al[0][1], al[0][2], al[0][3], aA + (GAT_AL_LO - GAT_AL_HI));
        LDSM_X4(al[1][0], al[1][1], al[1][2], al[1][3], aA + (GAT_AL_LO - GAT_AL_HI) + 16 * 32);
        uint32_t bA = bAddrBase + c * 16 * 64;
        LDSM_X4T(bh[0][0], bh[0][1], bh[0][2], bh[0][3], bA);
        LDSM_X4T(bh[1][0], bh[1][1], bh[1][2], bh[1][3], bA + 32);
        LDSM_X4T(bl[0][0], bl[0][1], bl[0][2], bl[0][3], bA + 16384);
        LDSM_X4T(bl[1][0], bl[1][1], bl[1][2], bl[1][3], bA + 16384 + 32);
#pragma unroll
        for (int mt = 0; mt < 2; mt++)
#pragma unroll
            for (int ng = 0; ng < 2; ng++)
#pragma unroll
                for (int hf = 0; hf < 2; hf++) {
                    float* dd = d[mt][ng * 2 + hf];
                    mma16816(dd, ah[mt], &bh[ng][hf * 2]);
                    mma16816(dd, ah[mt], &bl[ng][hf * 2]);
                    mma16816(dd, al[mt], &bh[ng][hf * 2]);
                }
    }

    sl_f[tid] = 1.f / l;    // l > 0 (self loop)
    __syncthreads();

    // ---- epilogue: scale, bias, split-bf16, write swizzled g_seq ----
    const int mtile = bt >> 7, mrow = bt & 127;
    unsigned char* seqh = (unsigned char*)g_seq_hi + (((size_t)mtile * 128) << 14);
    unsigned char* seql = (unsigned char*)g_seq_lo + (((size_t)mtile * 128) << 14);
#pragma unroll
    for (int mt = 0; mt < 2; mt++) {
        int r0 = i0 + mt * 16 + (lane >> 2);
        int r1 = r0 + 8;
        float inv0 = sl_f[r0], inv1 = sl_f[r1];
#pragma unroll
        for (int nt = 0; nt < 4; nt++) {
            int o = nt * 8 + (lane & 3) * 2;
            float b0 = sbias_f[o], b1 = sbias_f[o + 1];
            float v00 = fmaf(d[mt][nt][0], inv0, b0);
            float v01 = fmaf(d[mt][nt][1], inv0, b1);
            float v10 = fmaf(d[mt][nt][2], inv1, b0);
            float v11 = fmaf(d[mt][nt][3], inv1, b1);
            float h00, l00, h01, l01, h10, l10, h11, l11;
            split_bf16(v00, h00, l00); split_bf16(v01, h01, l01);
            split_bf16(v10, h10, l10); split_bf16(v11, h11, l11);
            {
                int k0 = r0 * 32 + o;
                uint32_t byte = (uint32_t)mrow * 128 + (k0 & 63) * 2;
                uint32_t sw = byte ^ ((byte >> 3) & 0x70);
                size_t off = ((size_t)(k0 >> 6) << 14) + sw;
                *(uint32_t*)(seqh + off) = pack_bf16x2(h00, h01);
                *(uint32_t*)(seql + off) = pack_bf16x2(l00, l01);
            }
            {
                int k1 = r1 * 32 + o;
                uint32_t byte = (uint32_t)mrow * 128 + (k1 & 63) * 2;
                uint32_t sw = byte ^ ((byte >> 3) & 0x70);
                size_t off = ((size_t)(k1 >> 6) << 14) + sw;
                *(uint32_t*)(seqh + off) = pack_bf16x2(h10, h11);
                *(uint32_t*)(seql + off) = pack_bf16x2(l10, l11);
            }
        }
    }
}

// ---------------------------------------------------------------------------
// Kernel 1b: W_ih fp32 -> swizzled tiled bf16 hi/lo (half rows per launch)
// ---------------------------------------------------------------------------
__global__ __launch_bounds__(256) void conv_wih_kernel(const float* __restrict__ W_ih, int n0)
{
    size_t t = (size_t)blockIdx.x * 256 + threadIdx.x;
    int n = n0 + (int)(t >> 10);
    int s = (int)(t & 1023);
    int k0 = s * 8;
    const float* src = W_ih + (size_t)n * GK + k0;
    float4 v0 = *(const float4*)(src);
    float4 v1 = *(const float4*)(src + 4);
    float f[8] = {v0.x, v0.y, v0.z, v0.w, v1.x, v1.y, v1.z, v1.w};
    float fh[8], fl[8];
#pragma unroll
    for (int i = 0; i < 8; i++) split_bf16(f[i], fh[i], fl[i]);

    int ntile = n >> 7, nrow = n & 127, chunk = s >> 3, seg = s & 7;
    size_t off = (((size_t)(ntile * 128 + chunk)) << 14) + nrow * 128
               + (uint32_t)((seg ^ (nrow & 7)) << 4);
    uint4 uh, ul;
    uh.x = pack_bf16x2(fh[0], fh[1]); uh.y = pack_bf16x2(fh[2], fh[3]);
    uh.z = pack_bf16x2(fh[4], fh[5]); uh.w = pack_bf16x2(fh[6], fh[7]);
    ul.x = pack_bf16x2(fl[0], fl[1]); ul.y = pack_bf16x2(fl[2], fl[3]);
    ul.z = pack_bf16x2(fl[4], fl[5]); ul.w = pack_bf16x2(fl[6], fl[7]);
    *(uint4*)((unsigned char*)g_wih_hi + off) = uh;
    *(uint4*)((unsigned char*)g_wih_lo + off) = ul;
}

// ---------------------------------------------------------------------------
// Kernel 1c: W_hh -> packed transpose
// ---------------------------------------------------------------------------
__global__ __launch_bounds__(256) void conv_whh_kernel(const float* __restrict__ W_hh)
{
    int t = blockIdx.x * 256 + threadIdx.x;
    int g  = t & 1023;
    int k4 = t >> 10;
    float4 v = *(const float4*)(W_hh + (size_t)g * Hz + k4 * 4);
    g_whhT[k4 * G4 + g] = v;
}

// ---------------------------------------------------------------------------
// Kernel 2: split-bf16 mma.sync GEMM fed by cp.async.bulk + mbarrier.
// ---------------------------------------------------------------------------
__global__ __launch_bounds__(256) void tc_gemm_kernel(
    const float* __restrict__ b_ih, const float* __restrict__ b_hh)
{
    extern __shared__ __align__(128) unsigned char dsmem[];
    __shared__ __align__(8) unsigned long long s_full[NSTAGE];
    const uint32_t dsm = smem_u32(dsmem);

    const int tid  = threadIdx.x;
    const int lane = tid & 31;
    const int wid  = tid >> 5;
    const int warp_m = wid >> 1;
    const int warp_n = wid & 1;
    const int mblk = blockIdx.y * BM;
    const int nblk = blockIdx.x * BN;
    const int mtile = blockIdx.y;
    const int ntile = blockIdx.x >> 1;
    const size_t bhalf = (size_t)(blockIdx.x & 1) * 8192;

    if (tid == 0) {
        for (int p = 0; p < NSTAGE; p++) MBARRIER_INIT(smem_u32(&s_full[p]), 1);
        FENCE_ASYNC();
    }
    __syncthreads();

    const unsigned char* srcAh = (const unsigned char*)g_seq_hi + (((size_t)mtile * 128) << 14);
    const unsigned char* srcAl = (const unsigned char*)g_seq_lo + (((size_t)mtile * 128) << 14);
    const unsigned char* srcBh = (const unsigned char*)g_wih_hi + (((size_t)ntile * 128) << 14) + bhalf;
    const unsigned char* srcBl = (const unsigned char*)g_wih_lo + (((size_t)ntile * 128) << 14) + bhalf;

    auto issue_stage = [&](int st, int it) {
        uint32_t sb = dsm + st * STAGE_B;
        uint32_t fb = smem_u32(&s_full[st]);
        size_t off = (size_t)it << 14;
        MBARRIER_EXPECT_TX(fb, STAGE_B);
        BULK_G2S(sb,          srcAh + off, 16384, fb);
        BULK_G2S(sb + OFF_AL, srcAl + off, 16384, fb);
        BULK_G2S(sb + OFF_BH, srcBh + off,  8192, fb);
        BULK_G2S(sb + OFF_BL, srcBl + off,  8192, fb);
    };

    if (tid == 0) {
        issue_stage(0, 0);
        issue_stage(1, 1);
        issue_stage(2, 2);
    }

    const int rA  = warp_m * 32 + (lane & 7) + ((lane >> 3) & 1) * 8;
    const int aHf = lane >> 4;
    const int r7a = rA & 7;
    const int rB  = warp_n * 32 + (lane & 7) + ((lane >> 4) & 1) * 8;
    const int bHf = (lane >> 3) & 1;
    const int r7b = rB & 7;
    const uint32_t aoff0 = (uint32_t)rA * 128;
    const uint32_t aoff1 = aoff0 + 16 * 128;
    const uint32_t boff0 = (uint32_t)rB * 128;
    const uint32_t boff1 = boff0 + 16 * 128;

    float d[2][4][4];
#pragma unroll
    for (int i = 0; i < 2; i++)
#pragma unroll
        for (int j = 0; j < 4; j++)
#pragma unroll
            for (int q = 0; q < 4; q++) d[i][j][q] = 0.f;

    for (int it = 0; it < NIT; it++) {
        int s = it % NSTAGE;
        MBARRIER_WAIT_PARITY(smem_u32(&s_full[s]), (it / NSTAGE) & 1);

        uint32_t sA = dsm + s * STAGE_B;
        uint32_t sB = sA + OFF_BH;
#pragma unroll
        for (int ks = 0; ks < 4; ks++) {
            int kseg = ks * 2;
            uint32_t ah[2][4], al[2][4], bh[2][4], bl[2][4];
            {
                uint32_t asg = (uint32_t)(((kseg + aHf) ^ r7a) << 4);
                uint32_t ad0 = sA + aoff0 + asg;
                uint32_t ad1 = sA + aoff1 + asg;
                LDSM_X4(ah[0][0], ah[0][1], ah[0][2], ah[0][3], ad0);
                LDSM_X4(ah[1][0], ah[1][1], ah[1][2], ah[1][3], ad1);
                LDSM_X4(al[0][0], al[0][1], al[0][2], al[0][3], ad0 + OFF_AL);
                LDSM_X4(al[1][0], al[1][1], al[1][2], al[1][3], ad1 + OFF_AL);
            }
            {
                uint32_t bsg = (uint32_t)(((kseg + bHf) ^ r7b) << 4);
                uint32_t bd0 = sB + boff0 + bsg;
                uint32_t bd1 = sB + boff1 + bsg;
                LDSM_X4(bh[0][0], bh[0][1], bh[0][2], bh[0][3], bd0);
                LDSM_X4(bh[1][0], bh[1][1], bh[1][2], bh[1][3], bd1);
                LDSM_X4(bl[0][0], bl[0][1], bl[0][2], bl[0][3], bd0 + 8192);
                LDSM_X4(bl[1][0], bl[1][1], bl[1][2], bl[1][3], bd1 + 8192);
            }
#pragma unroll
            for (int mt = 0; mt < 2; mt++)
#pragma unroll
                for (int p = 0; p < 2; p++)
#pragma unroll
                    for (int hf = 0; hf < 2; hf++) {
                        float* dd = d[mt][p * 2 + hf];
                        mma16816(dd, ah[mt], &bh[p][hf * 2]);
                        mma16816(dd, ah[mt], &bl[p][hf * 2]);
                        mma16816(dd, al[mt], &bh[p][hf * 2]);
                    }
        }
        __syncthreads();
        if (tid == 0 && it + NSTAGE < NIT) issue_stage(s, it + NSTAGE);
    }

#pragma unroll
    for (int mt = 0; mt < 2; mt++) {
#pragma unroll
        for (int nt = 0; nt < 4; nt++) {
            int rowm = mblk + warp_m * 32 + mt * 16 + (lane >> 2);
            int coln = nblk + warp_n * 32 + nt * 8 + (lane & 3) * 2;
            float bi0 = b_ih[coln]     + b_hh[coln];
            float bi1 = b_ih[coln + 1] + b_hh[coln + 1];
            float* p0 = g_gates + (size_t)rowm * GN + coln;
            float* p1 = g_gates + (size_t)(rowm + 8) * GN + coln;
            float2 v0 = {d[mt][nt][0] + bi0, d[mt][nt][1] + bi1};
            float2 v1 = {d[mt][nt][2] + bi0, d[mt][nt][3] + bi1};
            *(float2*)p0 = v0;
            *(float2*)p1 = v1;
        }
    }
}

// ---------------------------------------------------------------------------
// Kernel 3: LSTM recurrence (coalesced W_hh^T)
// ---------------------------------------------------------------------------
__global__ __launch_bounds__(1024) void lstm_kernel()
{
    __shared__ float hbuf[Hz];
    __shared__ float gbuf[G4];

    const int b = blockIdx.x;
    const int g = threadIdx.x;
    if (g < Hz) hbuf[g] = 0.f;
    float c = 0.f;

    const float* pre = g_gates + (size_t)b * Tz * G4;
    __syncthreads();

    for (int t = 0; t < Tz; t++) {
        float acc = pre[t * G4 + g];
#pragma unroll 16
        for (int k4 = 0; k4 < Hz / 4; k4++) {
            float4 w  = g_whhT[k4 * G4 + g];
            float4 h4 = *(const float4*)&hbuf[k4 * 4];
            acc = fmaf(w.x, h4.x, acc);
            acc = fmaf(w.y, h4.y, acc);
            acc = fmaf(w.z, h4.z, acc);
            acc = fmaf(w.w, h4.w, acc);
        }
        gbuf[g] = acc;
        __syncthreads();
        if (g < Hz) {
            float gi = 1.f / (1.f + __expf(-gbuf[g]));
            float gf = 1.f / (1.f + __expf(-gbuf[Hz + g]));
            float gg = tanhf(gbuf[2 * Hz + g]);
            float go = 1.f / (1.f + __expf(-gbuf[3 * Hz + g]));
            c = gf * c + gi * gg;
            hbuf[g] = go * tanhf(c);
        }
        __syncthreads();
    }
    if (g < Hz) g_hlast[b * Hz + g] = hbuf[g];
}

// ---------------------------------------------------------------------------
// Kernel 4: output linear
// ---------------------------------------------------------------------------
__global__ __launch_bounds__(256) void out_kernel(
    const float* __restrict__ Wo, const float* __restrict__ bo,
    float* __restrict__ out)
{
    const int b = blockIdx.x, n = threadIdx.x;
    const float4* h4 = (const float4*)(g_hlast + b * Hz);
    const float4* w4 = (const float4*)(Wo + n * Hz);
    float acc = bo[n];
#pragma unroll 8
    for (int k = 0; k < Hz / 4; k++) {
        float4 w = w4[k], h = h4[k];
        acc = fmaf(w.x, h.x, acc);
        acc = fmaf(w.y, h.y, acc);
        acc = fmaf(w.z, h.z, acc);
        acc = fmaf(w.w, h.w, acc);
    }
    out[b * Nz + n] = acc;
}

// ---------------------------------------------------------------------------
extern "C" void kernel_launch(void* const* d_in, const int* in_sizes, int n_in,
                              void* d_out, int out_size)
{
    const float* x     = (const float*)d_in[0];
    const float* adj   = (const float*)d_in[1];
    const float* W     = (const float*)d_in[2];
    const float* a_src = (const float*)d_in[3];
    const float* a_dst = (const float*)d_in[4];
    const float* gat_b = (const float*)d_in[5];
    const float* W_ih  = (const float*)d_in[6];
    const float* W_hh  = (const float*)d_in[7];
    const float* b_ih  = (const float*)d_in[8];
    const float* b_hh  = (const float*)d_in[9];
    const float* Wo    = (const float*)d_in[10];
    const float* bo    = (const float*)d_in[11];
    float* out = (float*)d_out;

    cudaFuncSetAttribute(tc_gemm_kernel,
                         cudaFuncAttributeMaxDynamicSharedMemorySize, SMEM_DYN);
    cudaFuncSetAttribute(gat_kernel,
                         cudaFuncAttributeMaxDynamicSharedMemorySize, SMEM_GAT);

    // index 3 = profiled slot -> gat (direct before/after comparison)
    conv_wih_kernel<<<2048, 256>>>(W_ih, 0);                              // 0
    conv_wih_kernel<<<2048, 256>>>(W_ih, 512);                            // 1
    conv_whh_kernel<<<256, 256>>>(W_hh);                                  // 2
    gat_kernel<<<GM, 256, SMEM_GAT>>>(x, adj, W, a_src, a_dst, gat_b);    // 3 (profiled)

    dim3 gg(GN / BN, GM / BM);
    tc_gemm_kernel<<<gg, 256, SMEM_DYN>>>(b_ih, b_hh);                    // 4

    lstm_kernel<<<Bz, 1024>>>();                                          // 5
    out_kernel<<<Bz, 256>>>(Wo, bo, out);                                 // 6
}